// round 2
// baseline (speedup 1.0000x reference)
#include <cuda_runtime.h>
#include <cstdint>

typedef unsigned long long ull;

// ---------------- packed f32x2 helpers (sm_100+ PTX ISA 8.6) ----------------
__device__ __forceinline__ void ffma2(ull& d, ull a, ull b) {
    asm("fma.rn.f32x2 %0, %1, %2, %0;" : "+l"(d) : "l"(a), "l"(b));
}
__device__ __forceinline__ ull fadd2(ull a, ull b) {
    ull d; asm("add.rn.f32x2 %0, %1, %2;" : "=l"(d) : "l"(a), "l"(b)); return d;
}
__device__ __forceinline__ ull pack2(float x, float y) {
    ull d; asm("mov.b64 %0, {%1, %2};" : "=l"(d) : "f"(x), "f"(y)); return d;
}
__device__ __forceinline__ float2 u2f(ull v) {
    float2 r; asm("mov.b64 {%0, %1}, %2;" : "=f"(r.x), "=f"(r.y) : "l"(v)); return r;
}
__device__ __forceinline__ float fast_sigmoid(float x) {
    float t;
    asm("tanh.approx.f32 %0, %1;" : "=f"(t) : "f"(x * 0.5f));
    return fmaf(t, 0.5f, 0.5f);
}

// ---------------- problem constants ----------------
#define RDIM 384
#define SDIM 2048
#define CE   64
#define HH   8
#define CC   8
#define HC   64
#define QSCALE 0.35355339059327373f   // sqrt(1/8)

// NOTE: a 64-float row = 256 bytes = 16 x ulonglong2 (each ulonglong2 = 4 floats)
#define ROW_U2 16

// scratch: o[r, h*C+c]
__device__ float g_o[RDIM * HC];

// dot of 64-float register row (16 x ulonglong2) with a 16B-aligned smem row
__device__ __forceinline__ float dot64(const ulonglong2* a, const ulonglong2* w) {
    ull d[4] = {0ull, 0ull, 0ull, 0ull};
#pragma unroll
    for (int i = 0; i < ROW_U2; i++) {
        ulonglong2 wv = w[i];
        ffma2(d[(2 * i) & 3],     a[i].x, wv.x);
        ffma2(d[(2 * i + 1) & 3], a[i].y, wv.y);
    }
    float2 f0 = u2f(d[0]), f1 = u2f(d[1]), f2v = u2f(d[2]), f3 = u2f(d[3]);
    return ((f0.x + f0.y) + (f1.x + f1.y)) + ((f2v.x + f2v.y) + (f3.x + f3.y));
}

// ============================================================================
// Kernel A: per-r attention. One CTA per r, 256 threads.
// smem (floats): k[8][2048] | v[8][2048] | msk[2048] | wk[512] | wv[512]
//                | qred[512] | dred[8] | qpool[64] | qproj[64]
// ============================================================================
#define OFF_K     0
#define OFF_V     16384
#define OFF_MSK   32768
#define OFF_WK    34816
#define OFF_WV    35328
#define OFF_QRED  35840
#define OFF_DRED  36352
#define OFF_QPOOL 36360
#define OFF_QPROJ 36424
#define SMEM_A_FLOATS 36488
#define SMEM_A_BYTES  (SMEM_A_FLOATS * 4)

__global__ void __launch_bounds__(256, 1)
attn_kernel(const float* __restrict__ m, const float* __restrict__ mask,
            const float* __restrict__ Wq, const float* __restrict__ Wk,
            const float* __restrict__ Wv) {
    extern __shared__ __align__(16) float sh[];
    float* k_sh   = sh + OFF_K;
    float* v_sh   = sh + OFF_V;
    float* msk_sh = sh + OFF_MSK;
    float* wk_sh  = sh + OFF_WK;
    float* wv_sh  = sh + OFF_WV;
    float* qred   = sh + OFF_QRED;
    float* dred   = sh + OFF_DRED;
    float* qpool  = sh + OFF_QPOOL;
    float* qproj  = sh + OFF_QPROJ;

    const int r    = blockIdx.x;
    const int tid  = threadIdx.x;
    const int lane = tid & 31;
    const int warp = tid >> 5;

    for (int i = tid; i < 512; i += 256) {
        wk_sh[i] = Wk[i];
        wv_sh[i] = Wv[i];
    }
    __syncthreads();

    // ---- phase 1: k, v projections + masked q pooling ----
    ull qn[32];                         // 32 packed pairs = 64 floats
#pragma unroll
    for (int i = 0; i < 32; i++) qn[i] = 0ull;
    float qden = 0.0f;

    const size_t mbase = (size_t)r * SDIM * CE;
#pragma unroll 1
    for (int it = 0; it < 8; ++it) {
        const int s = tid + it * 256;
        const ulonglong2* mr = (const ulonglong2*)(m + mbase + (size_t)s * CE);
        ulonglong2 a[ROW_U2];
#pragma unroll
        for (int i = 0; i < ROW_U2; i++) a[i] = mr[i];

        const float msk = mask[(size_t)r * SDIM + s];
        msk_sh[s] = msk;
        qden += msk;
        const ull mk = pack2(msk, msk);
#pragma unroll
        for (int i = 0; i < ROW_U2; i++) {
            ffma2(qn[2 * i],     a[i].x, mk);
            ffma2(qn[2 * i + 1], a[i].y, mk);
        }
#pragma unroll
        for (int c = 0; c < 8; c++) {
            k_sh[c * SDIM + s] = dot64(a, (const ulonglong2*)(wk_sh + c * 64));
            v_sh[c * SDIM + s] = dot64(a, (const ulonglong2*)(wv_sh + c * 64));
        }
    }

    // warp-reduce partial q sums
#pragma unroll
    for (int off = 16; off > 0; off >>= 1) {
#pragma unroll
        for (int i = 0; i < 32; i++)
            qn[i] = fadd2(qn[i], __shfl_xor_sync(0xffffffffu, qn[i], off));
        qden += __shfl_xor_sync(0xffffffffu, qden, off);
    }
    if (lane == 0) {
        ull* qredu = (ull*)qred;
#pragma unroll
        for (int i = 0; i < 32; i++) qredu[warp * 32 + i] = qn[i];
        dred[warp] = qden;
    }
    __syncthreads();

    if (tid < 64) {
        float qs = 0.0f;
#pragma unroll
        for (int w = 0; w < 8; w++) qs += qred[w * 64 + tid];
        float dt = 0.0f;
#pragma unroll
        for (int w = 0; w < 8; w++) dt += dred[w];
        qpool[tid] = qs / (dt + 1e-10f);
    }
    __syncthreads();
    if (tid < 64) {
        float acc = 0.0f;
        const float* wqr = Wq + tid * 64;
#pragma unroll
        for (int ce = 0; ce < 64; ce++) acc = fmaf(qpool[ce], wqr[ce], acc);
        qproj[tid] = acc * QSCALE;
    }
    __syncthreads();

    // ---- phase 2: attention per head (warp = head), two-pass softmax ----
    const int h = warp;
    float qh[8];
#pragma unroll
    for (int c = 0; c < 8; c++) qh[c] = qproj[h * 8 + c];

    float mx = -1e30f;
#pragma unroll 1
    for (int i = 0; i < 64; i++) {
        const int s = lane + 32 * i;
        float lg = (msk_sh[s] - 1.0f) * 1e9f;
#pragma unroll
        for (int c = 0; c < 8; c++) lg = fmaf(qh[c], k_sh[c * SDIM + s], lg);
        mx = fmaxf(mx, lg);
    }
#pragma unroll
    for (int off = 16; off > 0; off >>= 1)
        mx = fmaxf(mx, __shfl_xor_sync(0xffffffffu, mx, off));

    float sum = 0.0f;
    float acc[8];
#pragma unroll
    for (int c = 0; c < 8; c++) acc[c] = 0.0f;
#pragma unroll 1
    for (int i = 0; i < 64; i++) {
        const int s = lane + 32 * i;
        float lg = (msk_sh[s] - 1.0f) * 1e9f;
#pragma unroll
        for (int c = 0; c < 8; c++) lg = fmaf(qh[c], k_sh[c * SDIM + s], lg);
        const float e = __expf(lg - mx);
        sum += e;
#pragma unroll
        for (int c = 0; c < 8; c++) acc[c] = fmaf(e, v_sh[c * SDIM + s], acc[c]);
    }
#pragma unroll
    for (int off = 16; off > 0; off >>= 1) {
        sum += __shfl_xor_sync(0xffffffffu, sum, off);
#pragma unroll
        for (int c = 0; c < 8; c++)
            acc[c] += __shfl_xor_sync(0xffffffffu, acc[c], off);
    }
    if (lane == 0) {
        const float inv = 1.0f / sum;
#pragma unroll
        for (int c = 0; c < 8; c++)
            g_o[r * HC + h * 8 + c] = acc[c] * inv;
    }
}

// ============================================================================
// Kernel B: gate + output projection + residual. One thread per (r,s) row.
// grid = (S/256, R), 256 threads.
// ============================================================================
__global__ void __launch_bounds__(256, 1)
gate_kernel(const float* __restrict__ m, const float* __restrict__ Wg,
            const float* __restrict__ bg, const float* __restrict__ Wo,
            const float* __restrict__ bo, const float* __restrict__ add_to,
            float* __restrict__ out) {
    __shared__ __align__(16) float wg_sh[4096];
    __shared__ __align__(16) float wot_sh[4096];   // Wo^T: [hc][ce]
    __shared__ __align__(16) float o_sh[64];
    __shared__ __align__(16) float bg_sh[64];
    __shared__ __align__(16) float bo_sh[64];

    const int tid = threadIdx.x;
    const int r   = blockIdx.y;
    const int s   = blockIdx.x * 256 + tid;

    for (int i = tid; i < 4096; i += 256) {
        wg_sh[i] = Wg[i];
        const int hc = i >> 6, ce = i & 63;
        wot_sh[i] = Wo[ce * 64 + hc];
    }
    if (tid < 64) {
        o_sh[tid]  = g_o[r * HC + tid];
        bg_sh[tid] = bg[tid];
        bo_sh[tid] = bo[tid];
    }
    __syncthreads();

    const ulonglong2* mr = (const ulonglong2*)(m + ((size_t)r * SDIM + s) * CE);
    ulonglong2 a[ROW_U2];
#pragma unroll
    for (int i = 0; i < ROW_U2; i++) a[i] = mr[i];

    ull acc[32];                       // 32 packed pairs = 64 floats
#pragma unroll
    for (int i = 0; i < 32; i++) acc[i] = 0ull;

    const ulonglong2* wg2  = (const ulonglong2*)wg_sh;
    const ulonglong2* wot2 = (const ulonglong2*)wot_sh;

#pragma unroll 2
    for (int j = 0; j < 64; j++) {
        // g_j = sigmoid(m_row . Wg[j] + bg[j])
        ull d[4] = {0ull, 0ull, 0ull, 0ull};
        const ulonglong2* wr = wg2 + j * ROW_U2;
#pragma unroll
        for (int i = 0; i < ROW_U2; i++) {
            ulonglong2 wv = wr[i];
            ffma2(d[(2 * i) & 3],     a[i].x, wv.x);
            ffma2(d[(2 * i + 1) & 3], a[i].y, wv.y);
        }
        float2 f0 = u2f(d[0]), f1 = u2f(d[1]), f2v = u2f(d[2]), f3 = u2f(d[3]);
        const float dot = ((f0.x + f0.y) + (f1.x + f1.y)) + ((f2v.x + f2v.y) + (f3.x + f3.y));
        const float g = fast_sigmoid(dot + bg_sh[j]);
        const float t = g * o_sh[j];
        const ull tp = pack2(t, t);

        // out_vec += t * Wo^T[j][:]
        const ulonglong2* wo = wot2 + j * ROW_U2;
#pragma unroll
        for (int i = 0; i < ROW_U2; i++) {
            ulonglong2 wv = wo[i];
            ffma2(acc[2 * i],     tp, wv.x);
            ffma2(acc[2 * i + 1], tp, wv.y);
        }
    }

    // out[s, r, :] = add_to[s, r, :] + out_vec + bo
    const size_t obase = ((size_t)s * RDIM + r) * CE;
    const ulonglong2* add2 = (const ulonglong2*)(add_to + obase);
    const ulonglong2* bo2  = (const ulonglong2*)bo_sh;
    ulonglong2* out2 = (ulonglong2*)(out + obase);
#pragma unroll
    for (int i = 0; i < ROW_U2; i++) {
        ulonglong2 av = add2[i];
        ulonglong2 bv = bo2[i];
        ulonglong2 o;
        o.x = fadd2(fadd2(acc[2 * i],     av.x), bv.x);
        o.y = fadd2(fadd2(acc[2 * i + 1], av.y), bv.y);
        out2[i] = o;
    }
}

// ============================================================================
extern "C" void kernel_launch(void* const* d_in, const int* in_sizes, int n_in,
                              void* d_out, int out_size) {
    const float* m      = (const float*)d_in[0];
    const float* mask   = (const float*)d_in[1];
    const float* Wq     = (const float*)d_in[2];
    const float* Wk     = (const float*)d_in[3];
    const float* Wv     = (const float*)d_in[4];
    const float* Wg     = (const float*)d_in[5];
    const float* bg     = (const float*)d_in[6];
    const float* Wo     = (const float*)d_in[7];
    const float* bo     = (const float*)d_in[8];
    const float* add_to = (const float*)d_in[9];
    float* out = (float*)d_out;

    cudaFuncSetAttribute(attn_kernel, cudaFuncAttributeMaxDynamicSharedMemorySize,
                         SMEM_A_BYTES);

    attn_kernel<<<RDIM, 256, SMEM_A_BYTES>>>(m, mask, Wq, Wk, Wv);
    gate_kernel<<<dim3(SDIM / 256, RDIM), 256>>>(m, Wg, bg, Wo, bo, add_to, out);
}

// round 3
// speedup vs baseline: 1.0208x; 1.0208x over previous
#include <cuda_runtime.h>
#include <cstdint>

typedef unsigned long long ull;

// ---------------- packed f32x2 helpers ----------------
__device__ __forceinline__ void ffma2(ull& d, ull a, ull b) {
    asm("fma.rn.f32x2 %0, %1, %2, %0;" : "+l"(d) : "l"(a), "l"(b));
}
__device__ __forceinline__ ull fadd2(ull a, ull b) {
    ull d; asm("add.rn.f32x2 %0, %1, %2;" : "=l"(d) : "l"(a), "l"(b)); return d;
}
__device__ __forceinline__ ull pack2(float x, float y) {
    ull d; asm("mov.b64 %0, {%1, %2};" : "=l"(d) : "f"(x), "f"(y)); return d;
}
__device__ __forceinline__ float2 u2f(ull v) {
    float2 r; asm("mov.b64 {%0, %1}, %2;" : "=f"(r.x), "=f"(r.y) : "l"(v)); return r;
}
__device__ __forceinline__ float fast_sigmoid(float x) {
    float t;
    asm("tanh.approx.f32 %0, %1;" : "=f"(t) : "f"(x * 0.5f));
    return fmaf(t, 0.5f, 0.5f);
}

// ---------------- problem constants ----------------
#define RDIM 384
#define SDIM 2048
#define CE   64
#define HC   64
#define QSCALE 0.35355339059327373f
#define MST  66     // padded stride (floats) for staged 64-wide rows

__device__ float g_o[RDIM * HC];

// ============================================================================
// Kernel A: per-r attention. One CTA per r, 256 threads.
// ============================================================================
#define A_OFF_K     0
#define A_OFF_V     16384
#define A_OFF_MSK   32768
#define A_OFF_MLIN  34816          // 256 x 66
#define A_OFF_WT    51712          // wT16[k][c] 64x16
#define A_OFF_QRED  52736          // 8 x 64
#define A_OFF_DRED  53248
#define A_OFF_QPOOL 53256
#define A_OFF_QPROJ 53320
#define A_FLOATS    53384
#define A_BYTES     (A_FLOATS * 4)

__global__ void __launch_bounds__(256, 1)
attn_kernel(const float* __restrict__ m, const float* __restrict__ mask,
            const float* __restrict__ Wq, const float* __restrict__ Wk,
            const float* __restrict__ Wv) {
    extern __shared__ __align__(16) float sh[];
    float* k_sh   = sh + A_OFF_K;
    float* v_sh   = sh + A_OFF_V;
    float* msk_sh = sh + A_OFF_MSK;
    float* mlin   = sh + A_OFF_MLIN;
    float* wt     = sh + A_OFF_WT;
    float* qred   = sh + A_OFF_QRED;
    float* dred   = sh + A_OFF_DRED;
    float* qpool  = sh + A_OFF_QPOOL;
    float* qproj  = sh + A_OFF_QPROJ;

    const int r    = blockIdx.x;
    const int tid  = threadIdx.x;
    const int lane = tid & 31;
    const int warp = tid >> 5;

    // wT16[k][c]: c<8 -> Wk[c][k], else Wv[c-8][k]
    for (int i = tid; i < 1024; i += 256) {
        const int k = i >> 4, c = i & 15;
        wt[i] = (c < 8) ? Wk[c * 64 + k] : Wv[(c - 8) * 64 + k];
    }

    ull qn = 0ull;      // masked m-sum for ce = (2*lane, 2*lane+1)
    float qden = 0.0f;

    const int ct = tid & 3, c0 = 4 * ct;
    const int stl = (tid >> 2) * 4;   // 0..252

    // ---- phase 1: tiled load + k/v projection GEMM ----
#pragma unroll 1
    for (int tile = 0; tile < 8; ++tile) {
        __syncthreads();
        const int sbase = tile * 256;
        // coalesced load: warp handles 32 rows, lane loads float2 at ce=2*lane
#pragma unroll 4
        for (int i = 0; i < 32; i++) {
            const int srow = warp * 32 + i;
            const int sg   = sbase + srow;
            const ull mv = *(const ull*)(m + ((size_t)r * SDIM + sg) * CE + 2 * lane);
            const float msk = mask[(size_t)r * SDIM + sg];
            ffma2(qn, mv, pack2(msk, msk));
            qden += msk;
            if (lane == 0) msk_sh[sg] = msk;
            *(ull*)&mlin[srow * MST + 2 * lane] = mv;
        }
        __syncthreads();

        // kv GEMM: thread micro-tile 4s x 4c
        ull acc[2][4];
#pragma unroll
        for (int cp = 0; cp < 2; cp++)
#pragma unroll
            for (int si = 0; si < 4; si++) acc[cp][si] = 0ull;

#pragma unroll 4
        for (int k = 0; k < 64; k++) {
            const ulonglong2 wv = *(const ulonglong2*)&wt[k * 16 + c0];
#pragma unroll
            for (int si = 0; si < 4; si++) {
                const float mv = mlin[(stl + si) * MST + k];
                const ull mp = pack2(mv, mv);
                ffma2(acc[0][si], wv.x, mp);
                ffma2(acc[1][si], wv.y, mp);
            }
        }
        // scatter to k_sh/v_sh [c][s]
#pragma unroll
        for (int cp = 0; cp < 2; cp++) {
#pragma unroll
            for (int si = 0; si < 4; si++) {
                const float2 f = u2f(acc[cp][si]);
                const int c  = c0 + 2 * cp;
                const int sg = sbase + stl + si;
                if (c < 8)  k_sh[c * SDIM + sg] = f.x;
                else        v_sh[(c - 8) * SDIM + sg] = f.x;
                if (c + 1 < 8) k_sh[(c + 1) * SDIM + sg] = f.y;
                else           v_sh[(c + 1 - 8) * SDIM + sg] = f.y;
            }
        }
    }

    // ---- q pool reduce ----
    ((ull*)qred)[warp * 32 + lane] = qn;          // qred[w][ce]
    if (lane == 0) dred[warp] = qden;
    __syncthreads();

    if (tid < 64) {
        float qs = 0.0f;
#pragma unroll
        for (int w = 0; w < 8; w++) qs += qred[w * 64 + tid];
        float dt = 0.0f;
#pragma unroll
        for (int w = 0; w < 8; w++) dt += dred[w];
        qpool[tid] = qs / (dt + 1e-10f);
    }
    __syncthreads();
    if (tid < 64) {
        float acc = 0.0f;
        const float* wqr = Wq + tid * 64;
#pragma unroll
        for (int ce = 0; ce < 64; ce++) acc = fmaf(qpool[ce], wqr[ce], acc);
        qproj[tid] = acc * QSCALE;
    }
    __syncthreads();

    // ---- phase 2: attention per head (warp = head), two-pass softmax ----
    const int h = warp;
    float qh[8];
#pragma unroll
    for (int c = 0; c < 8; c++) qh[c] = qproj[h * 8 + c];

    float mx = -1e30f;
#pragma unroll 1
    for (int i = 0; i < 64; i++) {
        const int s = lane + 32 * i;
        float lg = (msk_sh[s] - 1.0f) * 1e9f;
#pragma unroll
        for (int c = 0; c < 8; c++) lg = fmaf(qh[c], k_sh[c * SDIM + s], lg);
        mx = fmaxf(mx, lg);
    }
#pragma unroll
    for (int off = 16; off > 0; off >>= 1)
        mx = fmaxf(mx, __shfl_xor_sync(0xffffffffu, mx, off));

    float sum = 0.0f;
    float oacc[8];
#pragma unroll
    for (int c = 0; c < 8; c++) oacc[c] = 0.0f;
#pragma unroll 1
    for (int i = 0; i < 64; i++) {
        const int s = lane + 32 * i;
        float lg = (msk_sh[s] - 1.0f) * 1e9f;
#pragma unroll
        for (int c = 0; c < 8; c++) lg = fmaf(qh[c], k_sh[c * SDIM + s], lg);
        const float e = __expf(lg - mx);
        sum += e;
#pragma unroll
        for (int c = 0; c < 8; c++) oacc[c] = fmaf(e, v_sh[c * SDIM + s], oacc[c]);
    }
#pragma unroll
    for (int off = 16; off > 0; off >>= 1) {
        sum += __shfl_xor_sync(0xffffffffu, sum, off);
#pragma unroll
        for (int c = 0; c < 8; c++)
            oacc[c] += __shfl_xor_sync(0xffffffffu, oacc[c], off);
    }
    if (lane == 0) {
        const float inv = 1.0f / sum;
#pragma unroll
        for (int c = 0; c < 8; c++)
            g_o[r * HC + h * 8 + c] = oacc[c] * inv;
    }
}

// ============================================================================
// Kernel B: gate + output projection + residual. Register-tiled GEMMs.
// CTA handles (r, 256-row s-tile). 256 threads, micro-tile 8s x 8j / 8s x 8ce.
// ============================================================================
#define B_OFF_MLIN 0
#define B_OFF_TLIN 16896
#define B_OFF_WG   33792      // wgT[k][j]  (64x64)
#define B_OFF_WO   37888      // woT[j][ce] (64x64)
#define B_FLOATS   41984
#define B_BYTES    (B_FLOATS * 4)

__global__ void __launch_bounds__(256, 1)
gate_kernel(const float* __restrict__ m, const float* __restrict__ Wg,
            const float* __restrict__ bg, const float* __restrict__ Wo,
            const float* __restrict__ bo, const float* __restrict__ add_to,
            float* __restrict__ out) {
    extern __shared__ __align__(16) float sh[];
    float* mlin = sh + B_OFF_MLIN;
    float* tlin = sh + B_OFF_TLIN;
    float* wgT  = sh + B_OFF_WG;
    float* woT  = sh + B_OFF_WO;

    const int tid   = threadIdx.x;
    const int lane  = tid & 31;
    const int warp  = tid >> 5;
    const int r     = blockIdx.y;
    const int sbase = blockIdx.x * 256;

    // transpose weights into smem
    for (int i = tid; i < 4096; i += 256) {
        const int a = i >> 6, b = i & 63;
        wgT[i] = Wg[b * 64 + a];     // wgT[k][j] = Wg[j][k]
        woT[i] = Wo[b * 64 + a];     // woT[j][ce] = Wo[ce][j]
    }
    // coalesced m tile load
#pragma unroll 4
    for (int i = 0; i < 32; i++) {
        const int srow = warp * 32 + i;
        *(ull*)&mlin[srow * MST + 2 * lane] =
            *(const ull*)(m + ((size_t)r * SDIM + sbase + srow) * CE + 2 * lane);
    }
    __syncthreads();

    const int g8 = (tid & 7) * 8;      // j0 (GEMM1) / ce0 (GEMM2)
    const int st = (tid >> 3) * 8;     // s micro-tile base

    // ---- GEMM1: gate logits, acc[jp][si], pairs along j ----
    ull acc[4][8];
#pragma unroll
    for (int jp = 0; jp < 4; jp++)
#pragma unroll
        for (int si = 0; si < 8; si++) acc[jp][si] = 0ull;

#pragma unroll 2
    for (int k = 0; k < 64; k++) {
        const ulonglong2 wa = *(const ulonglong2*)&wgT[k * 64 + g8];
        const ulonglong2 wb = *(const ulonglong2*)&wgT[k * 64 + g8 + 4];
#pragma unroll
        for (int si = 0; si < 8; si++) {
            const float mv = mlin[(st + si) * MST + k];
            const ull mp = pack2(mv, mv);
            ffma2(acc[0][si], wa.x, mp);
            ffma2(acc[1][si], wa.y, mp);
            ffma2(acc[2][si], wb.x, mp);
            ffma2(acc[3][si], wb.y, mp);
        }
    }

    // ---- sigmoid gate * o, store t to smem ----
    float ov[8], bgv[8];
#pragma unroll
    for (int jj = 0; jj < 8; jj++) {
        ov[jj]  = g_o[r * HC + g8 + jj];
        bgv[jj] = bg[g8 + jj];
    }
#pragma unroll
    for (int si = 0; si < 8; si++) {
#pragma unroll
        for (int jp = 0; jp < 4; jp++) {
            const float2 f = u2f(acc[jp][si]);
            const float t0 = fast_sigmoid(f.x + bgv[2 * jp])     * ov[2 * jp];
            const float t1 = fast_sigmoid(f.y + bgv[2 * jp + 1]) * ov[2 * jp + 1];
            *(ull*)&tlin[(st + si) * MST + g8 + 2 * jp] = pack2(t0, t1);
        }
    }
    __syncthreads();

    // ---- GEMM2: out projection, acc2[cp][si], pairs along ce ----
    ull acc2[4][8];
#pragma unroll
    for (int cp = 0; cp < 4; cp++)
#pragma unroll
        for (int si = 0; si < 8; si++) acc2[cp][si] = 0ull;

#pragma unroll 2
    for (int j = 0; j < 64; j++) {
        const ulonglong2 wa = *(const ulonglong2*)&woT[j * 64 + g8];
        const ulonglong2 wb = *(const ulonglong2*)&woT[j * 64 + g8 + 4];
#pragma unroll
        for (int si = 0; si < 8; si++) {
            const float tv = tlin[(st + si) * MST + j];
            const ull tp = pack2(tv, tv);
            ffma2(acc2[0][si], wa.x, tp);
            ffma2(acc2[1][si], wa.y, tp);
            ffma2(acc2[2][si], wb.x, tp);
            ffma2(acc2[3][si], wb.y, tp);
        }
    }

    // ---- epilogue: + add_to + bo, write out[s][r][ce] ----
    ull bop[4];
#pragma unroll
    for (int cp = 0; cp < 4; cp++) bop[cp] = pack2(bo[g8 + 2 * cp], bo[g8 + 2 * cp + 1]);

#pragma unroll
    for (int si = 0; si < 8; si++) {
        const size_t base = ((size_t)(sbase + st + si) * RDIM + r) * CE + g8;
        const ulonglong2 a0 = *(const ulonglong2*)(add_to + base);
        const ulonglong2 a1 = *(const ulonglong2*)(add_to + base + 4);
        ulonglong2 o0, o1;
        o0.x = fadd2(fadd2(acc2[0][si], a0.x), bop[0]);
        o0.y = fadd2(fadd2(acc2[1][si], a0.y), bop[1]);
        o1.x = fadd2(fadd2(acc2[2][si], a1.x), bop[2]);
        o1.y = fadd2(fadd2(acc2[3][si], a1.y), bop[3]);
        *(ulonglong2*)(out + base)     = o0;
        *(ulonglong2*)(out + base + 4) = o1;
    }
}

// ============================================================================
extern "C" void kernel_launch(void* const* d_in, const int* in_sizes, int n_in,
                              void* d_out, int out_size) {
    const float* m      = (const float*)d_in[0];
    const float* mask   = (const float*)d_in[1];
    const float* Wq     = (const float*)d_in[2];
    const float* Wk     = (const float*)d_in[3];
    const float* Wv     = (const float*)d_in[4];
    const float* Wg     = (const float*)d_in[5];
    const float* bg     = (const float*)d_in[6];
    const float* Wo     = (const float*)d_in[7];
    const float* bo     = (const float*)d_in[8];
    const float* add_to = (const float*)d_in[9];
    float* out = (float*)d_out;

    cudaFuncSetAttribute(attn_kernel, cudaFuncAttributeMaxDynamicSharedMemorySize, A_BYTES);
    cudaFuncSetAttribute(gate_kernel, cudaFuncAttributeMaxDynamicSharedMemorySize, B_BYTES);

    attn_kernel<<<RDIM, 256, A_BYTES>>>(m, mask, Wq, Wk, Wv);
    gate_kernel<<<dim3(SDIM / 256, RDIM), 256, B_BYTES>>>(m, Wg, bg, Wo, bo, add_to, out);
}

// round 5
// speedup vs baseline: 1.4214x; 1.3925x over previous
#include <cuda_runtime.h>
#include <cuda_bf16.h>
#include <cstdint>

typedef unsigned long long ull;
typedef unsigned int uint;

// ================= generic helpers =================
__device__ __forceinline__ void ffma2(ull& d, ull a, ull b) {
    asm("fma.rn.f32x2 %0, %1, %2, %0;" : "+l"(d) : "l"(a), "l"(b));
}
__device__ __forceinline__ ull pack2(float x, float y) {
    ull d; asm("mov.b64 %0, {%1, %2};" : "=l"(d) : "f"(x), "f"(y)); return d;
}
__device__ __forceinline__ float2 u2f(ull v) {
    float2 r; asm("mov.b64 {%0, %1}, %2;" : "=f"(r.x), "=f"(r.y) : "l"(v)); return r;
}
__device__ __forceinline__ float fast_sigmoid(float x) {
    float t;
    asm("tanh.approx.f32 %0, %1;" : "=f"(t) : "f"(x * 0.5f));
    return fmaf(t, 0.5f, 0.5f);
}
__device__ __forceinline__ uint bfpack(float x, float y) {
    __nv_bfloat16 bx = __float2bfloat16(x), by = __float2bfloat16(y);
    return (uint)__bfloat16_as_ushort(bx) | ((uint)__bfloat16_as_ushort(by) << 16);
}
// split (x,y) into bf16 hi pair + bf16 residual pair
__device__ __forceinline__ void split2(float x, float y, uint& hi, uint& lo) {
    __nv_bfloat16 hx = __float2bfloat16(x), hy = __float2bfloat16(y);
    hi = (uint)__bfloat16_as_ushort(hx) | ((uint)__bfloat16_as_ushort(hy) << 16);
    lo = bfpack(x - __bfloat162float(hx), y - __bfloat162float(hy));
}
__device__ __forceinline__ void mma_bf16(float* d, const uint* a, uint b0, uint b1) {
    asm volatile(
        "mma.sync.aligned.m16n8k16.row.col.f32.bf16.bf16.f32 "
        "{%0,%1,%2,%3}, {%4,%5,%6,%7}, {%8,%9}, {%0,%1,%2,%3};"
        : "+f"(d[0]), "+f"(d[1]), "+f"(d[2]), "+f"(d[3])
        : "r"(a[0]), "r"(a[1]), "r"(a[2]), "r"(a[3]), "r"(b0), "r"(b1));
}

// ================= problem constants =================
#define RDIM 384
#define SDIM 2048
#define CE   64
#define HC   64
#define QSCALE 0.35355339059327373f
#define MST  66

__device__ float g_o[RDIM * HC];

// ============================================================================
// Kernel A: per-r attention. One CTA per r, 256 threads. (unchanged, passing)
// ============================================================================
#define A_OFF_K     0
#define A_OFF_V     16384
#define A_OFF_MSK   32768
#define A_OFF_MLIN  34816
#define A_OFF_WT    51712
#define A_OFF_QRED  52736
#define A_OFF_DRED  53248
#define A_OFF_QPOOL 53256
#define A_OFF_QPROJ 53320
#define A_FLOATS    53384
#define A_BYTES     (A_FLOATS * 4)

__global__ void __launch_bounds__(256, 1)
attn_kernel(const float* __restrict__ m, const float* __restrict__ mask,
            const float* __restrict__ Wq, const float* __restrict__ Wk,
            const float* __restrict__ Wv) {
    extern __shared__ __align__(16) float sh[];
    float* k_sh   = sh + A_OFF_K;
    float* v_sh   = sh + A_OFF_V;
    float* msk_sh = sh + A_OFF_MSK;
    float* mlin   = sh + A_OFF_MLIN;
    float* wt     = sh + A_OFF_WT;
    float* qred   = sh + A_OFF_QRED;
    float* dred   = sh + A_OFF_DRED;
    float* qpool  = sh + A_OFF_QPOOL;
    float* qproj  = sh + A_OFF_QPROJ;

    const int r    = blockIdx.x;
    const int tid  = threadIdx.x;
    const int lane = tid & 31;
    const int warp = tid >> 5;

    for (int i = tid; i < 1024; i += 256) {
        const int k = i >> 4, c = i & 15;
        wt[i] = (c < 8) ? Wk[c * 64 + k] : Wv[(c - 8) * 64 + k];
    }

    ull qn = 0ull;
    float qden = 0.0f;

    const int ct = tid & 3, c0 = 4 * ct;
    const int stl = (tid >> 2) * 4;

#pragma unroll 1
    for (int tile = 0; tile < 8; ++tile) {
        __syncthreads();
        const int sbase = tile * 256;
#pragma unroll 4
        for (int i = 0; i < 32; i++) {
            const int srow = warp * 32 + i;
            const int sg   = sbase + srow;
            const ull mv = *(const ull*)(m + ((size_t)r * SDIM + sg) * CE + 2 * lane);
            const float msk = mask[(size_t)r * SDIM + sg];
            ffma2(qn, mv, pack2(msk, msk));
            qden += msk;
            if (lane == 0) msk_sh[sg] = msk;
            *(ull*)&mlin[srow * MST + 2 * lane] = mv;
        }
        __syncthreads();

        ull acc[2][4];
#pragma unroll
        for (int cp = 0; cp < 2; cp++)
#pragma unroll
            for (int si = 0; si < 4; si++) acc[cp][si] = 0ull;

#pragma unroll 4
        for (int k = 0; k < 64; k++) {
            const ulonglong2 wv = *(const ulonglong2*)&wt[k * 16 + c0];
#pragma unroll
            for (int si = 0; si < 4; si++) {
                const float mv = mlin[(stl + si) * MST + k];
                const ull mp = pack2(mv, mv);
                ffma2(acc[0][si], wv.x, mp);
                ffma2(acc[1][si], wv.y, mp);
            }
        }
#pragma unroll
        for (int cp = 0; cp < 2; cp++) {
#pragma unroll
            for (int si = 0; si < 4; si++) {
                const float2 f = u2f(acc[cp][si]);
                const int c  = c0 + 2 * cp;
                const int sg = sbase + stl + si;
                if (c < 8)  k_sh[c * SDIM + sg] = f.x;
                else        v_sh[(c - 8) * SDIM + sg] = f.x;
                if (c + 1 < 8) k_sh[(c + 1) * SDIM + sg] = f.y;
                else           v_sh[(c + 1 - 8) * SDIM + sg] = f.y;
            }
        }
    }

    ((ull*)qred)[warp * 32 + lane] = qn;
    if (lane == 0) dred[warp] = qden;
    __syncthreads();

    if (tid < 64) {
        float qs = 0.0f;
#pragma unroll
        for (int w = 0; w < 8; w++) qs += qred[w * 64 + tid];
        float dt = 0.0f;
#pragma unroll
        for (int w = 0; w < 8; w++) dt += dred[w];
        qpool[tid] = qs / (dt + 1e-10f);
    }
    __syncthreads();
    if (tid < 64) {
        float acc = 0.0f;
        const float* wqr = Wq + tid * 64;
#pragma unroll
        for (int ce = 0; ce < 64; ce++) acc = fmaf(qpool[ce], wqr[ce], acc);
        qproj[tid] = acc * QSCALE;
    }
    __syncthreads();

    const int h = warp;
    float qh[8];
#pragma unroll
    for (int c = 0; c < 8; c++) qh[c] = qproj[h * 8 + c];

    float mx = -1e30f;
#pragma unroll 1
    for (int i = 0; i < 64; i++) {
        const int s = lane + 32 * i;
        float lg = (msk_sh[s] - 1.0f) * 1e9f;
#pragma unroll
        for (int c = 0; c < 8; c++) lg = fmaf(qh[c], k_sh[c * SDIM + s], lg);
        mx = fmaxf(mx, lg);
    }
#pragma unroll
    for (int off = 16; off > 0; off >>= 1)
        mx = fmaxf(mx, __shfl_xor_sync(0xffffffffu, mx, off));

    float sum = 0.0f;
    float oacc[8];
#pragma unroll
    for (int c = 0; c < 8; c++) oacc[c] = 0.0f;
#pragma unroll 1
    for (int i = 0; i < 64; i++) {
        const int s = lane + 32 * i;
        float lg = (msk_sh[s] - 1.0f) * 1e9f;
#pragma unroll
        for (int c = 0; c < 8; c++) lg = fmaf(qh[c], k_sh[c * SDIM + s], lg);
        const float e = __expf(lg - mx);
        sum += e;
#pragma unroll
        for (int c = 0; c < 8; c++) oacc[c] = fmaf(e, v_sh[c * SDIM + s], oacc[c]);
    }
#pragma unroll
    for (int off = 16; off > 0; off >>= 1) {
        sum += __shfl_xor_sync(0xffffffffu, sum, off);
#pragma unroll
        for (int c = 0; c < 8; c++)
            oacc[c] += __shfl_xor_sync(0xffffffffu, oacc[c], off);
    }
    if (lane == 0) {
        const float inv = 1.0f / sum;
#pragma unroll
        for (int c = 0; c < 8; c++)
            g_o[r * HC + h * 8 + c] = oacc[c] * inv;
    }
}

// ============================================================================
// Kernel B (HMMA mma.sync bf16 hi/lo): gate + out projection + residual.
// CTA = (r, 128-row s-tile), 128 threads / 4 warps; warp owns 32 rows.
// A and t tiles: bf16 [128][72] hi+lo. Weights: bf16 [64][72] hi+lo.
// D = A @ W^T via mma.m16n8k16.row.col (B frag read from row-major [n][k]).
// ============================================================================
#define ASTW 36          // row stride in 32-bit words (72 bf16)
#define GB_A_HI 0
#define GB_A_LO 18432
#define GB_WG_HI 36864
#define GB_WG_LO 46080
#define GB_WO_HI 55296
#define GB_WO_LO 64512
#define GB_VEC   73728   // bg[64], oo[64], bo[64] floats
#define GB_SIZE  (GB_VEC + 3 * 256)

__global__ void __launch_bounds__(128, 1)
gate_kernel(const float* __restrict__ m, const float* __restrict__ Wg,
            const float* __restrict__ bg, const float* __restrict__ Wo,
            const float* __restrict__ bo, const float* __restrict__ add_to,
            float* __restrict__ out) {
    extern __shared__ __align__(16) unsigned char sg[];
    uint* a_hi  = (uint*)(sg + GB_A_HI);
    uint* a_lo  = (uint*)(sg + GB_A_LO);
    uint* wg_hi = (uint*)(sg + GB_WG_HI);
    uint* wg_lo = (uint*)(sg + GB_WG_LO);
    uint* wo_hi = (uint*)(sg + GB_WO_HI);
    uint* wo_lo = (uint*)(sg + GB_WO_LO);
    float* bg_sh = (float*)(sg + GB_VEC);
    float* oo_sh = bg_sh + 64;
    float* bo_sh = bg_sh + 128;

    const int tid  = threadIdx.x;
    const int lane = tid & 31;
    const int warp = tid >> 5;
    const int g    = lane >> 2;     // row group 0..7
    const int tg   = lane & 3;      // thread-in-group
    const int r     = blockIdx.y;
    const int sbase = blockIdx.x * 128;

    // ---- stage weights (hi/lo bf16) ----
    for (int i = tid; i < 2048; i += 128) {
        const int row = i >> 5, kp = i & 31;   // kp = k-pair
        {
            float2 w = *(const float2*)(Wg + row * 64 + kp * 2);
            uint hi, lo; split2(w.x, w.y, hi, lo);
            wg_hi[row * ASTW + kp] = hi;
            wg_lo[row * ASTW + kp] = lo;
        }
        {
            float2 w = *(const float2*)(Wo + row * 64 + kp * 2);
            uint hi, lo; split2(w.x, w.y, hi, lo);
            wo_hi[row * ASTW + kp] = hi;
            wo_lo[row * ASTW + kp] = lo;
        }
    }
    // ---- stage m tile (hi/lo bf16), warp w owns rows [32w, 32w+32) ----
#pragma unroll 4
    for (int i = 0; i < 32; i++) {
        const int row = warp * 32 + i;
        float2 v = *(const float2*)(m + ((size_t)r * SDIM + sbase + row) * CE + 2 * lane);
        uint hi, lo; split2(v.x, v.y, hi, lo);
        a_hi[row * ASTW + lane] = hi;
        a_lo[row * ASTW + lane] = lo;
    }
    if (tid < 64) {
        bg_sh[tid] = bg[tid];
        oo_sh[tid] = g_o[r * HC + tid];
        bo_sh[tid] = bo[tid];
    }
    __syncthreads();

    const int rowbase = warp * 32;
    float d[2][8][4];

    // ================= GEMM1: gate logits = m @ Wg^T =================
#pragma unroll
    for (int mt = 0; mt < 2; mt++)
#pragma unroll
        for (int nt = 0; nt < 8; nt++)
#pragma unroll
            for (int q = 0; q < 4; q++) d[mt][nt][q] = 0.0f;

#pragma unroll
    for (int p = 0; p < 3; p++) {
        const uint* ab = (p == 2) ? a_lo : a_hi;
        const uint* wb = (p == 1) ? wg_lo : wg_hi;
#pragma unroll
        for (int kt = 0; kt < 4; kt++) {
            uint a[2][4];
#pragma unroll
            for (int mt = 0; mt < 2; mt++) {
                const int r0 = rowbase + mt * 16 + g;
                a[mt][0] = ab[r0 * ASTW + kt * 8 + tg];
                a[mt][1] = ab[(r0 + 8) * ASTW + kt * 8 + tg];
                a[mt][2] = ab[r0 * ASTW + kt * 8 + tg + 4];
                a[mt][3] = ab[(r0 + 8) * ASTW + kt * 8 + tg + 4];
            }
#pragma unroll
            for (int nt = 0; nt < 8; nt++) {
                const uint b0 = wb[(nt * 8 + g) * ASTW + kt * 8 + tg];
                const uint b1 = wb[(nt * 8 + g) * ASTW + kt * 8 + tg + 4];
                mma_bf16(d[0][nt], a[0], b0, b1);
                mma_bf16(d[1][nt], a[1], b0, b1);
            }
        }
    }

    // ---- epilogue 1: t = sigmoid(d+bg)*o -> bf16 hi/lo back over A tile ----
#pragma unroll
    for (int mt = 0; mt < 2; mt++) {
#pragma unroll
        for (int nt = 0; nt < 8; nt++) {
            const int c0 = nt * 8 + tg * 2;
            const float b0v = bg_sh[c0], b1v = bg_sh[c0 + 1];
            const float o0v = oo_sh[c0], o1v = oo_sh[c0 + 1];
            const int r0 = rowbase + mt * 16 + g;
            {
                const float t0 = fast_sigmoid(d[mt][nt][0] + b0v) * o0v;
                const float t1 = fast_sigmoid(d[mt][nt][1] + b1v) * o1v;
                uint hi, lo; split2(t0, t1, hi, lo);
                a_hi[r0 * ASTW + nt * 4 + tg] = hi;
                a_lo[r0 * ASTW + nt * 4 + tg] = lo;
            }
            {
                const float t0 = fast_sigmoid(d[mt][nt][2] + b0v) * o0v;
                const float t1 = fast_sigmoid(d[mt][nt][3] + b1v) * o1v;
                uint hi, lo; split2(t0, t1, hi, lo);
                a_hi[(r0 + 8) * ASTW + nt * 4 + tg] = hi;
                a_lo[(r0 + 8) * ASTW + nt * 4 + tg] = lo;
            }
        }
    }
    __syncwarp();   // t rows are warp-private; order STS before LDS within warp

    // ================= GEMM2: out = t @ Wo^T =================
#pragma unroll
    for (int mt = 0; mt < 2; mt++)
#pragma unroll
        for (int nt = 0; nt < 8; nt++)
#pragma unroll
            for (int q = 0; q < 4; q++) d[mt][nt][q] = 0.0f;

#pragma unroll
    for (int p = 0; p < 3; p++) {
        const uint* ab = (p == 2) ? a_lo : a_hi;
        const uint* wb = (p == 1) ? wo_lo : wo_hi;
#pragma unroll
        for (int kt = 0; kt < 4; kt++) {
            uint a[2][4];
#pragma unroll
            for (int mt = 0; mt < 2; mt++) {
                const int r0 = rowbase + mt * 16 + g;
                a[mt][0] = ab[r0 * ASTW + kt * 8 + tg];
                a[mt][1] = ab[(r0 + 8) * ASTW + kt * 8 + tg];
                a[mt][2] = ab[r0 * ASTW + kt * 8 + tg + 4];
                a[mt][3] = ab[(r0 + 8) * ASTW + kt * 8 + tg + 4];
            }
#pragma unroll
            for (int nt = 0; nt < 8; nt++) {
                const uint b0 = wb[(nt * 8 + g) * ASTW + kt * 8 + tg];
                const uint b1 = wb[(nt * 8 + g) * ASTW + kt * 8 + tg + 4];
                mma_bf16(d[0][nt], a[0], b0, b1);
                mma_bf16(d[1][nt], a[1], b0, b1);
            }
        }
    }

    // ---- epilogue 2: out[s][r][:] = D + bo + add_to ----
#pragma unroll
    for (int mt = 0; mt < 2; mt++) {
#pragma unroll
        for (int nt = 0; nt < 8; nt++) {
            const int c0 = nt * 8 + tg * 2;
            const float bo0 = bo_sh[c0], bo1 = bo_sh[c0 + 1];
            const int r0 = rowbase + mt * 16 + g;
            {
                const size_t base = ((size_t)(sbase + r0) * RDIM + r) * CE + c0;
                const float2 av = *(const float2*)(add_to + base);
                float2 ov;
                ov.x = d[mt][nt][0] + bo0 + av.x;
                ov.y = d[mt][nt][1] + bo1 + av.y;
                *(float2*)(out + base) = ov;
            }
            {
                const size_t base = ((size_t)(sbase + r0 + 8) * RDIM + r) * CE + c0;
                const float2 av = *(const float2*)(add_to + base);
                float2 ov;
                ov.x = d[mt][nt][2] + bo0 + av.x;
                ov.y = d[mt][nt][3] + bo1 + av.y;
                *(float2*)(out + base) = ov;
            }
        }
    }
}

// ============================================================================
extern "C" void kernel_launch(void* const* d_in, const int* in_sizes, int n_in,
                              void* d_out, int out_size) {
    const float* m      = (const float*)d_in[0];
    const float* mask   = (const float*)d_in[1];
    const float* Wq     = (const float*)d_in[2];
    const float* Wk     = (const float*)d_in[3];
    const float* Wv     = (const float*)d_in[4];
    const float* Wg     = (const float*)d_in[5];
    const float* bg     = (const float*)d_in[6];
    const float* Wo     = (const float*)d_in[7];
    const float* bo     = (const float*)d_in[8];
    const float* add_to = (const float*)d_in[9];
    float* out = (float*)d_out;

    cudaFuncSetAttribute(attn_kernel, cudaFuncAttributeMaxDynamicSharedMemorySize, A_BYTES);
    cudaFuncSetAttribute(gate_kernel, cudaFuncAttributeMaxDynamicSharedMemorySize, GB_SIZE);

    attn_kernel<<<RDIM, 256, A_BYTES>>>(m, mask, Wq, Wk, Wv);
    gate_kernel<<<dim3(SDIM / 128, RDIM), 128, GB_SIZE>>>(m, Wg, bg, Wo, bo, add_to, out);
}

// round 6
// speedup vs baseline: 1.6306x; 1.1472x over previous
#include <cuda_runtime.h>
#include <cuda_bf16.h>
#include <cstdint>

typedef unsigned long long ull;
typedef unsigned int uint;

// ================= helpers =================
__device__ __forceinline__ void ffma2(ull& d, ull a, ull b) {
    asm("fma.rn.f32x2 %0, %1, %2, %0;" : "+l"(d) : "l"(a), "l"(b));
}
__device__ __forceinline__ ull pack2(float x, float y) {
    ull d; asm("mov.b64 %0, {%1, %2};" : "=l"(d) : "f"(x), "f"(y)); return d;
}
__device__ __forceinline__ float2 u2f(ull v) {
    float2 r; asm("mov.b64 {%0, %1}, %2;" : "=f"(r.x), "=f"(r.y) : "l"(v)); return r;
}
__device__ __forceinline__ float fast_sigmoid(float x) {
    float t;
    asm("tanh.approx.f32 %0, %1;" : "=f"(t) : "f"(x * 0.5f));
    return fmaf(t, 0.5f, 0.5f);
}
__device__ __forceinline__ uint bfpack(float x, float y) {
    __nv_bfloat16 bx = __float2bfloat16(x), by = __float2bfloat16(y);
    return (uint)__bfloat16_as_ushort(bx) | ((uint)__bfloat16_as_ushort(by) << 16);
}
__device__ __forceinline__ void split2(float x, float y, uint& hi, uint& lo) {
    __nv_bfloat16 hx = __float2bfloat16(x), hy = __float2bfloat16(y);
    hi = (uint)__bfloat16_as_ushort(hx) | ((uint)__bfloat16_as_ushort(hy) << 16);
    lo = bfpack(x - __bfloat162float(hx), y - __bfloat162float(hy));
}
__device__ __forceinline__ void mma_bf16(float* d, const uint* a, uint b0, uint b1) {
    asm volatile(
        "mma.sync.aligned.m16n8k16.row.col.f32.bf16.bf16.f32 "
        "{%0,%1,%2,%3}, {%4,%5,%6,%7}, {%8,%9}, {%0,%1,%2,%3};"
        : "+f"(d[0]), "+f"(d[1]), "+f"(d[2]), "+f"(d[3])
        : "r"(a[0]), "r"(a[1]), "r"(a[2]), "r"(a[3]), "r"(b0), "r"(b1));
}

// ================= constants =================
#define RDIM 384
#define SDIM 2048
#define CE   64
#define HC   64
#define QSCALE 0.35355339059327373f
#define NCH  8        // s-chunks per r in kernel L
#define CHUNK 256

// ================= scratch =================
__device__ float g_o[RDIM * HC];
__device__ float g_qk[RDIM * 512];          // [r][e][h]
__device__ float g_am[RDIM * NCH * 8 * 64]; // [r][ch][h][e]
__device__ float g_mx[RDIM * NCH * 8];      // [r][ch][h]
__device__ float g_sm[RDIM * NCH * 8];

// ============================================================================
// Kernel Q: masked mean-pool -> q -> qk.  One CTA per r, 256 threads.
// ============================================================================
__global__ void __launch_bounds__(256, 4)
qpool_kernel(const float* __restrict__ m, const float* __restrict__ mask,
             const float* __restrict__ Wq, const float* __restrict__ Wk) {
    __shared__ float qred[8 * 64];
    __shared__ float dred[8];
    __shared__ float qpool[64];
    __shared__ float qproj[64];

    const int r    = blockIdx.x;
    const int tid  = threadIdx.x;
    const int lane = tid & 31;
    const int warp = tid >> 5;

    ull qn = 0ull;
    float qden = 0.0f;

    const size_t mbase = (size_t)r * SDIM * CE;
#pragma unroll 1
    for (int tile = 0; tile < 8; ++tile) {
        const int sbase = tile * 256;
#pragma unroll 4
        for (int i = 0; i < 32; i++) {
            const int sg = sbase + warp * 32 + i;
            const ull mv = *(const ull*)(m + mbase + (size_t)sg * CE + 2 * lane);
            const float msk = mask[(size_t)r * SDIM + sg];
            ffma2(qn, mv, pack2(msk, msk));
            qden += msk;
        }
    }
    ((ull*)qred)[warp * 32 + lane] = qn;
    if (lane == 0) dred[warp] = qden;
    __syncthreads();

    if (tid < 64) {
        float qs = 0.0f;
#pragma unroll
        for (int w = 0; w < 8; w++) qs += qred[w * 64 + tid];
        float dt = 0.0f;
#pragma unroll
        for (int w = 0; w < 8; w++) dt += dred[w];
        qpool[tid] = qs / (dt + 1e-10f);
    }
    __syncthreads();
    if (tid < 64) {
        float acc = 0.0f;
        const float* wqr = Wq + tid * 64;
#pragma unroll
        for (int e = 0; e < 64; e++) acc = fmaf(qpool[e], wqr[e], acc);
        qproj[tid] = acc * QSCALE;
    }
    __syncthreads();

    // qk[e][h] = sum_c q[h*8+c] * Wk[c][e]   (tid = e*... : 512 values, 2 rounds)
    for (int i = tid; i < 512; i += 256) {
        const int e = i >> 3, h = i & 7;
        float acc = 0.0f;
#pragma unroll
        for (int c = 0; c < 8; c++) acc = fmaf(qproj[h * 8 + c], Wk[c * 64 + e], acc);
        g_qk[r * 512 + i] = acc;
    }
}

// ============================================================================
// Kernel L: per (chunk, r): logits + chunk softmax partials + partial am.
// 256 threads; thread t owns s-row t of the 256-row chunk.
// ============================================================================
#define L_MST 66
#define L_OFF_M   0
#define L_OFF_A   16896          // a_sh[256][8]
#define L_OFF_QK  18944          // qk_sh[512]
#define L_OFF_WRD 19456          // wred[64]
#define L_OFF_MX  19520          // mx_sh[8]
#define L_FLOATS  19528
#define L_BYTES   (L_FLOATS * 4)

__global__ void __launch_bounds__(256, 2)
logits_kernel(const float* __restrict__ m, const float* __restrict__ mask) {
    extern __shared__ __align__(16) float shl[];
    float* m_sh  = shl + L_OFF_M;
    float* a_sh  = shl + L_OFF_A;
    float* qk_sh = shl + L_OFF_QK;
    float* wred  = shl + L_OFF_WRD;
    float* mx_sh = shl + L_OFF_MX;

    const int tid  = threadIdx.x;
    const int lane = tid & 31;
    const int warp = tid >> 5;
    const int ch   = blockIdx.x;
    const int r    = blockIdx.y;
    const int sbase = ch * CHUNK;

    // qk stage
    for (int i = tid; i < 512; i += 256) qk_sh[i] = g_qk[r * 512 + i];

    // m chunk stage (coalesced: warp row-block, lane = ce pair)
    const size_t mbase = ((size_t)r * SDIM + sbase) * CE;
#pragma unroll 4
    for (int i = 0; i < 32; i++) {
        const int row = warp * 32 + i;
        *(ull*)&m_sh[row * L_MST + 2 * lane] = *(const ull*)(m + mbase + (size_t)row * CE + 2 * lane);
    }
    const float mymsk = mask[(size_t)r * SDIM + sbase + tid];
    __syncthreads();

    // logits for own row
    float lg[8];
    const float bias = (mymsk - 1.0f) * 1e9f;
#pragma unroll
    for (int h = 0; h < 8; h++) lg[h] = bias;
#pragma unroll 4
    for (int e = 0; e < 64; e++) {
        const float mv = m_sh[tid * L_MST + e];
        const float4 qa = *(const float4*)&qk_sh[e * 8];
        const float4 qb = *(const float4*)&qk_sh[e * 8 + 4];
        lg[0] = fmaf(mv, qa.x, lg[0]);
        lg[1] = fmaf(mv, qa.y, lg[1]);
        lg[2] = fmaf(mv, qa.z, lg[2]);
        lg[3] = fmaf(mv, qa.w, lg[3]);
        lg[4] = fmaf(mv, qb.x, lg[4]);
        lg[5] = fmaf(mv, qb.y, lg[5]);
        lg[6] = fmaf(mv, qb.z, lg[6]);
        lg[7] = fmaf(mv, qb.w, lg[7]);
    }

    // chunk max per h
    float wm[8];
#pragma unroll
    for (int h = 0; h < 8; h++) {
        float v = lg[h];
#pragma unroll
        for (int off = 16; off > 0; off >>= 1)
            v = fmaxf(v, __shfl_xor_sync(0xffffffffu, v, off));
        wm[h] = v;
    }
    if (lane == 0)
#pragma unroll
        for (int h = 0; h < 8; h++) wred[warp * 8 + h] = wm[h];
    __syncthreads();
    if (tid < 8) {
        float v = -1e30f;
#pragma unroll
        for (int w = 0; w < 8; w++) v = fmaxf(v, wred[w * 8 + tid]);
        mx_sh[tid] = v;
    }
    __syncthreads();

    // exp + chunk sum per h, stash a
    float sm[8];
#pragma unroll
    for (int h = 0; h < 8; h++) {
        const float e = __expf(lg[h] - mx_sh[h]);
        a_sh[tid * 8 + h] = e;
        float v = e;
#pragma unroll
        for (int off = 16; off > 0; off >>= 1)
            v += __shfl_xor_sync(0xffffffffu, v, off);
        sm[h] = v;
    }
    __syncthreads();   // wred reuse
    if (lane == 0)
#pragma unroll
        for (int h = 0; h < 8; h++) wred[warp * 8 + h] = sm[h];
    __syncthreads();
    if (tid < 8) {
        float v = 0.0f;
#pragma unroll
        for (int w = 0; w < 8; w++) v += wred[w * 8 + tid];
        g_sm[(r * NCH + ch) * 8 + tid] = v;
        g_mx[(r * NCH + ch) * 8 + tid] = mx_sh[tid];
    }

    // partial am[h][e] = sum_s a[s][h] * m[s][e];  warp = h, lane = e-pair
    const int h = warp;
    ull am = 0ull;
#pragma unroll 4
    for (int s = 0; s < CHUNK; s++) {
        const float a = a_sh[s * 8 + h];
        const ull mp = *(const ull*)&m_sh[s * L_MST + 2 * lane];
        ffma2(am, mp, pack2(a, a));
    }
    *(ull*)&g_am[((r * NCH + ch) * 8 + h) * 64 + 2 * lane] = am;
}

// ============================================================================
// Kernel C: combine chunks + o = am @ Wv^T -> g_o.  384 CTAs x 64 threads.
// ============================================================================
__global__ void __launch_bounds__(64, 8)
combine_kernel(const float* __restrict__ Wv) {
    __shared__ float wgt[8][8];   // [h][ch]
    __shared__ float den[8];
    __shared__ float am_sh[8 * 64];

    const int r   = blockIdx.x;
    const int tid = threadIdx.x;

    if (tid < 8) {
        const int h = tid;
        float mxg = -1e30f;
#pragma unroll
        for (int c = 0; c < NCH; c++) mxg = fmaxf(mxg, g_mx[(r * NCH + c) * 8 + h]);
        float d = 0.0f;
#pragma unroll
        for (int c = 0; c < NCH; c++) {
            const float w = __expf(g_mx[(r * NCH + c) * 8 + h] - mxg);
            wgt[h][c] = w;
            d = fmaf(g_sm[(r * NCH + c) * 8 + h], w, d);
        }
        den[h] = d;
    }
    __syncthreads();

    // am_g: 512 values / 64 threads = 8 each
    {
        const int h = tid >> 3, e0 = (tid & 7) * 8;
#pragma unroll
        for (int e = 0; e < 8; e++) {
            float s = 0.0f;
#pragma unroll
            for (int c = 0; c < NCH; c++)
                s = fmaf(g_am[((r * NCH + c) * 8 + h) * 64 + e0 + e], wgt[h][c], s);
            am_sh[h * 64 + e0 + e] = s;
        }
    }
    __syncthreads();

    // o[h][cc] = (am[h] . Wv[cc]) / den[h]
    {
        const int h = tid >> 3, cc = tid & 7;
        float acc = 0.0f;
        const float* wvr = Wv + cc * 64;
        const float* amr = am_sh + h * 64;
#pragma unroll
        for (int e = 0; e < 64; e++) acc = fmaf(amr[e], wvr[e], acc);
        g_o[r * HC + h * 8 + cc] = acc / den[tid >> 3];
    }
}

// ============================================================================
// Kernel B (HMMA bf16 hi/lo): gate + out projection + residual. (round-5 code,
// now with min-blocks 3 to push occupancy)
// ============================================================================
#define ASTW 36
#define GB_A_HI 0
#define GB_A_LO 18432
#define GB_WG_HI 36864
#define GB_WG_LO 46080
#define GB_WO_HI 55296
#define GB_WO_LO 64512
#define GB_VEC   73728
#define GB_SIZE  (GB_VEC + 3 * 256)

__global__ void __launch_bounds__(128, 3)
gate_kernel(const float* __restrict__ m, const float* __restrict__ Wg,
            const float* __restrict__ bg, const float* __restrict__ Wo,
            const float* __restrict__ bo, const float* __restrict__ add_to,
            float* __restrict__ out) {
    extern __shared__ __align__(16) unsigned char sg[];
    uint* a_hi  = (uint*)(sg + GB_A_HI);
    uint* a_lo  = (uint*)(sg + GB_A_LO);
    uint* wg_hi = (uint*)(sg + GB_WG_HI);
    uint* wg_lo = (uint*)(sg + GB_WG_LO);
    uint* wo_hi = (uint*)(sg + GB_WO_HI);
    uint* wo_lo = (uint*)(sg + GB_WO_LO);
    float* bg_sh = (float*)(sg + GB_VEC);
    float* oo_sh = bg_sh + 64;
    float* bo_sh = bg_sh + 128;

    const int tid  = threadIdx.x;
    const int lane = tid & 31;
    const int warp = tid >> 5;
    const int g    = lane >> 2;
    const int tg   = lane & 3;
    const int r     = blockIdx.y;
    const int sbase = blockIdx.x * 128;

    for (int i = tid; i < 2048; i += 128) {
        const int row = i >> 5, kp = i & 31;
        {
            float2 w = *(const float2*)(Wg + row * 64 + kp * 2);
            uint hi, lo; split2(w.x, w.y, hi, lo);
            wg_hi[row * ASTW + kp] = hi;
            wg_lo[row * ASTW + kp] = lo;
        }
        {
            float2 w = *(const float2*)(Wo + row * 64 + kp * 2);
            uint hi, lo; split2(w.x, w.y, hi, lo);
            wo_hi[row * ASTW + kp] = hi;
            wo_lo[row * ASTW + kp] = lo;
        }
    }
#pragma unroll 4
    for (int i = 0; i < 32; i++) {
        const int row = warp * 32 + i;
        float2 v = *(const float2*)(m + ((size_t)r * SDIM + sbase + row) * CE + 2 * lane);
        uint hi, lo; split2(v.x, v.y, hi, lo);
        a_hi[row * ASTW + lane] = hi;
        a_lo[row * ASTW + lane] = lo;
    }
    if (tid < 64) {
        bg_sh[tid] = bg[tid];
        oo_sh[tid] = g_o[r * HC + tid];
        bo_sh[tid] = bo[tid];
    }
    __syncthreads();

    const int rowbase = warp * 32;
    float d[2][8][4];

    // GEMM1
#pragma unroll
    for (int mt = 0; mt < 2; mt++)
#pragma unroll
        for (int nt = 0; nt < 8; nt++)
#pragma unroll
            for (int q = 0; q < 4; q++) d[mt][nt][q] = 0.0f;

#pragma unroll
    for (int p = 0; p < 3; p++) {
        const uint* ab = (p == 2) ? a_lo : a_hi;
        const uint* wb = (p == 1) ? wg_lo : wg_hi;
#pragma unroll
        for (int kt = 0; kt < 4; kt++) {
            uint a[2][4];
#pragma unroll
            for (int mt = 0; mt < 2; mt++) {
                const int r0 = rowbase + mt * 16 + g;
                a[mt][0] = ab[r0 * ASTW + kt * 8 + tg];
                a[mt][1] = ab[(r0 + 8) * ASTW + kt * 8 + tg];
                a[mt][2] = ab[r0 * ASTW + kt * 8 + tg + 4];
                a[mt][3] = ab[(r0 + 8) * ASTW + kt * 8 + tg + 4];
            }
#pragma unroll
            for (int nt = 0; nt < 8; nt++) {
                const uint b0 = wb[(nt * 8 + g) * ASTW + kt * 8 + tg];
                const uint b1 = wb[(nt * 8 + g) * ASTW + kt * 8 + tg + 4];
                mma_bf16(d[0][nt], a[0], b0, b1);
                mma_bf16(d[1][nt], a[1], b0, b1);
            }
        }
    }

    // epilogue 1
#pragma unroll
    for (int mt = 0; mt < 2; mt++) {
#pragma unroll
        for (int nt = 0; nt < 8; nt++) {
            const int c0 = nt * 8 + tg * 2;
            const float b0v = bg_sh[c0], b1v = bg_sh[c0 + 1];
            const float o0v = oo_sh[c0], o1v = oo_sh[c0 + 1];
            const int r0 = rowbase + mt * 16 + g;
            {
                const float t0 = fast_sigmoid(d[mt][nt][0] + b0v) * o0v;
                const float t1 = fast_sigmoid(d[mt][nt][1] + b1v) * o1v;
                uint hi, lo; split2(t0, t1, hi, lo);
                a_hi[r0 * ASTW + nt * 4 + tg] = hi;
                a_lo[r0 * ASTW + nt * 4 + tg] = lo;
            }
            {
                const float t0 = fast_sigmoid(d[mt][nt][2] + b0v) * o0v;
                const float t1 = fast_sigmoid(d[mt][nt][3] + b1v) * o1v;
                uint hi, lo; split2(t0, t1, hi, lo);
                a_hi[(r0 + 8) * ASTW + nt * 4 + tg] = hi;
                a_lo[(r0 + 8) * ASTW + nt * 4 + tg] = lo;
            }
        }
    }
    __syncwarp();

    // GEMM2
#pragma unroll
    for (int mt = 0; mt < 2; mt++)
#pragma unroll
        for (int nt = 0; nt < 8; nt++)
#pragma unroll
            for (int q = 0; q < 4; q++) d[mt][nt][q] = 0.0f;

#pragma unroll
    for (int p = 0; p < 3; p++) {
        const uint* ab = (p == 2) ? a_lo : a_hi;
        const uint* wb = (p == 1) ? wo_lo : wo_hi;
#pragma unroll
        for (int kt = 0; kt < 4; kt++) {
            uint a[2][4];
#pragma unroll
            for (int mt = 0; mt < 2; mt++) {
                const int r0 = rowbase + mt * 16 + g;
                a[mt][0] = ab[r0 * ASTW + kt * 8 + tg];
                a[mt][1] = ab[(r0 + 8) * ASTW + kt * 8 + tg];
                a[mt][2] = ab[r0 * ASTW + kt * 8 + tg + 4];
                a[mt][3] = ab[(r0 + 8) * ASTW + kt * 8 + tg + 4];
            }
#pragma unroll
            for (int nt = 0; nt < 8; nt++) {
                const uint b0 = wb[(nt * 8 + g) * ASTW + kt * 8 + tg];
                const uint b1 = wb[(nt * 8 + g) * ASTW + kt * 8 + tg + 4];
                mma_bf16(d[0][nt], a[0], b0, b1);
                mma_bf16(d[1][nt], a[1], b0, b1);
            }
        }
    }

    // epilogue 2
#pragma unroll
    for (int mt = 0; mt < 2; mt++) {
#pragma unroll
        for (int nt = 0; nt < 8; nt++) {
            const int c0 = nt * 8 + tg * 2;
            const float bo0 = bo_sh[c0], bo1 = bo_sh[c0 + 1];
            const int r0 = rowbase + mt * 16 + g;
            {
                const size_t base = ((size_t)(sbase + r0) * RDIM + r) * CE + c0;
                const float2 av = *(const float2*)(add_to + base);
                float2 ov;
                ov.x = d[mt][nt][0] + bo0 + av.x;
                ov.y = d[mt][nt][1] + bo1 + av.y;
                *(float2*)(out + base) = ov;
            }
            {
                const size_t base = ((size_t)(sbase + r0 + 8) * RDIM + r) * CE + c0;
                const float2 av = *(const float2*)(add_to + base);
                float2 ov;
                ov.x = d[mt][nt][2] + bo0 + av.x;
                ov.y = d[mt][nt][3] + bo1 + av.y;
                *(float2*)(out + base) = ov;
            }
        }
    }
}

// ============================================================================
extern "C" void kernel_launch(void* const* d_in, const int* in_sizes, int n_in,
                              void* d_out, int out_size) {
    const float* m      = (const float*)d_in[0];
    const float* mask   = (const float*)d_in[1];
    const float* Wq     = (const float*)d_in[2];
    const float* Wk     = (const float*)d_in[3];
    const float* Wv     = (const float*)d_in[4];
    const float* Wg     = (const float*)d_in[5];
    const float* bg     = (const float*)d_in[6];
    const float* Wo     = (const float*)d_in[7];
    const float* bo     = (const float*)d_in[8];
    const float* add_to = (const float*)d_in[9];
    float* out = (float*)d_out;

    cudaFuncSetAttribute(logits_kernel, cudaFuncAttributeMaxDynamicSharedMemorySize, L_BYTES);
    cudaFuncSetAttribute(gate_kernel, cudaFuncAttributeMaxDynamicSharedMemorySize, GB_SIZE);

    qpool_kernel<<<RDIM, 256>>>(m, mask, Wq, Wk);
    logits_kernel<<<dim3(NCH, RDIM), 256, L_BYTES>>>(m, mask);
    combine_kernel<<<RDIM, 64>>>(Wv);
    gate_kernel<<<dim3(SDIM / 128, RDIM), 128, GB_SIZE>>>(m, Wg, bg, Wo, bo, add_to, out);
}

// round 7
// speedup vs baseline: 2.0126x; 1.2342x over previous
#include <cuda_runtime.h>
#include <cuda_bf16.h>
#include <cstdint>

typedef unsigned long long ull;
typedef unsigned int uint;

// ================= helpers =================
__device__ __forceinline__ void ffma2(ull& d, ull a, ull b) {
    asm("fma.rn.f32x2 %0, %1, %2, %0;" : "+l"(d) : "l"(a), "l"(b));
}
__device__ __forceinline__ ull pack2(float x, float y) {
    ull d; asm("mov.b64 %0, {%1, %2};" : "=l"(d) : "f"(x), "f"(y)); return d;
}
__device__ __forceinline__ float fast_sigmoid(float x) {
    float t;
    asm("tanh.approx.f32 %0, %1;" : "=f"(t) : "f"(x * 0.5f));
    return fmaf(t, 0.5f, 0.5f);
}
__device__ __forceinline__ uint bfpack(float x, float y) {
    __nv_bfloat16 bx = __float2bfloat16(x), by = __float2bfloat16(y);
    return (uint)__bfloat16_as_ushort(bx) | ((uint)__bfloat16_as_ushort(by) << 16);
}
__device__ __forceinline__ void split2(float x, float y, uint& hi, uint& lo) {
    __nv_bfloat16 hx = __float2bfloat16(x), hy = __float2bfloat16(y);
    hi = (uint)__bfloat16_as_ushort(hx) | ((uint)__bfloat16_as_ushort(hy) << 16);
    lo = bfpack(x - __bfloat162float(hx), y - __bfloat162float(hy));
}
__device__ __forceinline__ void mma_bf16(float* d, const uint* a, uint b0, uint b1) {
    asm volatile(
        "mma.sync.aligned.m16n8k16.row.col.f32.bf16.bf16.f32 "
        "{%0,%1,%2,%3}, {%4,%5,%6,%7}, {%8,%9}, {%0,%1,%2,%3};"
        : "+f"(d[0]), "+f"(d[1]), "+f"(d[2]), "+f"(d[3])
        : "r"(a[0]), "r"(a[1]), "r"(a[2]), "r"(a[3]), "r"(b0), "r"(b1));
}
__device__ __forceinline__ uint smem_u32(const void* p) {
    uint a;
    asm("{ .reg .u64 t; cvta.to.shared.u64 t, %1; cvt.u32.u64 %0, t; }" : "=r"(a) : "l"(p));
    return a;
}
__device__ __forceinline__ void cp_async16(uint saddr, const void* gptr) {
    asm volatile("cp.async.cg.shared.global [%0], [%1], 16;" :: "r"(saddr), "l"(gptr));
}
#define CP_COMMIT() asm volatile("cp.async.commit_group;" ::: "memory")
#define CP_WAIT0()  asm volatile("cp.async.wait_group 0;" ::: "memory")

// ================= constants =================
#define RDIM 384
#define SDIM 2048
#define CE   64
#define HC   64
#define QSCALE 0.35355339059327373f
#define NCH  8
#define CHUNK 256

// ================= scratch =================
__device__ float g_o[RDIM * HC];
__device__ float g_qk[RDIM * 512];
__device__ float g_am[RDIM * NCH * 8 * 64];
__device__ float g_mx[RDIM * NCH * 8];
__device__ float g_sm[RDIM * NCH * 8];

// ============================================================================
// Kernel Q: masked mean-pool -> q -> qk.  One CTA per r, 256 threads.
// ============================================================================
__global__ void __launch_bounds__(256, 4)
qpool_kernel(const float* __restrict__ m, const float* __restrict__ mask,
             const float* __restrict__ Wq, const float* __restrict__ Wk) {
    __shared__ float qred[8 * 64];
    __shared__ float dred[8];
    __shared__ float qpool[64];
    __shared__ float qproj[64];

    const int r    = blockIdx.x;
    const int tid  = threadIdx.x;
    const int lane = tid & 31;
    const int warp = tid >> 5;

    ull qn = 0ull;
    float qden = 0.0f;

    const size_t mbase = (size_t)r * SDIM * CE;
#pragma unroll 1
    for (int tile = 0; tile < 8; ++tile) {
        const int sbase = tile * 256;
#pragma unroll 4
        for (int i = 0; i < 32; i++) {
            const int sg = sbase + warp * 32 + i;
            const ull mv = *(const ull*)(m + mbase + (size_t)sg * CE + 2 * lane);
            const float msk = mask[(size_t)r * SDIM + sg];
            ffma2(qn, mv, pack2(msk, msk));
            qden += msk;
        }
    }
    ((ull*)qred)[warp * 32 + lane] = qn;
    if (lane == 0) dred[warp] = qden;
    __syncthreads();

    if (tid < 64) {
        float qs = 0.0f;
#pragma unroll
        for (int w = 0; w < 8; w++) qs += qred[w * 64 + tid];
        float dt = 0.0f;
#pragma unroll
        for (int w = 0; w < 8; w++) dt += dred[w];
        qpool[tid] = qs / (dt + 1e-10f);
    }
    __syncthreads();
    if (tid < 64) {
        float acc = 0.0f;
        const float* wqr = Wq + tid * 64;
#pragma unroll
        for (int e = 0; e < 64; e++) acc = fmaf(qpool[e], wqr[e], acc);
        qproj[tid] = acc * QSCALE;
    }
    __syncthreads();

    for (int i = tid; i < 512; i += 256) {
        const int e = i >> 3, h = i & 7;
        float acc = 0.0f;
#pragma unroll
        for (int c = 0; c < 8; c++) acc = fmaf(qproj[h * 8 + c], Wk[c * 64 + e], acc);
        g_qk[r * 512 + i] = acc;
    }
}

// ============================================================================
// Kernel L: per (chunk, r): logits + chunk softmax partials + partial am.
// ============================================================================
#define L_MST 66
#define L_OFF_M   0
#define L_OFF_A   16896
#define L_OFF_QK  18944
#define L_OFF_WRD 19456
#define L_OFF_MX  19520
#define L_FLOATS  19528
#define L_BYTES   (L_FLOATS * 4)

__global__ void __launch_bounds__(256, 2)
logits_kernel(const float* __restrict__ m, const float* __restrict__ mask) {
    extern __shared__ __align__(16) float shl[];
    float* m_sh  = shl + L_OFF_M;
    float* a_sh  = shl + L_OFF_A;
    float* qk_sh = shl + L_OFF_QK;
    float* wred  = shl + L_OFF_WRD;
    float* mx_sh = shl + L_OFF_MX;

    const int tid  = threadIdx.x;
    const int lane = tid & 31;
    const int warp = tid >> 5;
    const int ch   = blockIdx.x;
    const int r    = blockIdx.y;
    const int sbase = ch * CHUNK;

    for (int i = tid; i < 512; i += 256) qk_sh[i] = g_qk[r * 512 + i];

    const size_t mbase = ((size_t)r * SDIM + sbase) * CE;
#pragma unroll 4
    for (int i = 0; i < 32; i++) {
        const int row = warp * 32 + i;
        *(ull*)&m_sh[row * L_MST + 2 * lane] = *(const ull*)(m + mbase + (size_t)row * CE + 2 * lane);
    }
    const float mymsk = mask[(size_t)r * SDIM + sbase + tid];
    __syncthreads();

    float lg[8];
    const float bias = (mymsk - 1.0f) * 1e9f;
#pragma unroll
    for (int h = 0; h < 8; h++) lg[h] = bias;
#pragma unroll 4
    for (int e = 0; e < 64; e++) {
        const float mv = m_sh[tid * L_MST + e];
        const float4 qa = *(const float4*)&qk_sh[e * 8];
        const float4 qb = *(const float4*)&qk_sh[e * 8 + 4];
        lg[0] = fmaf(mv, qa.x, lg[0]);
        lg[1] = fmaf(mv, qa.y, lg[1]);
        lg[2] = fmaf(mv, qa.z, lg[2]);
        lg[3] = fmaf(mv, qa.w, lg[3]);
        lg[4] = fmaf(mv, qb.x, lg[4]);
        lg[5] = fmaf(mv, qb.y, lg[5]);
        lg[6] = fmaf(mv, qb.z, lg[6]);
        lg[7] = fmaf(mv, qb.w, lg[7]);
    }

    float wm[8];
#pragma unroll
    for (int h = 0; h < 8; h++) {
        float v = lg[h];
#pragma unroll
        for (int off = 16; off > 0; off >>= 1)
            v = fmaxf(v, __shfl_xor_sync(0xffffffffu, v, off));
        wm[h] = v;
    }
    if (lane == 0)
#pragma unroll
        for (int h = 0; h < 8; h++) wred[warp * 8 + h] = wm[h];
    __syncthreads();
    if (tid < 8) {
        float v = -1e30f;
#pragma unroll
        for (int w = 0; w < 8; w++) v = fmaxf(v, wred[w * 8 + tid]);
        mx_sh[tid] = v;
    }
    __syncthreads();

    float sm[8];
#pragma unroll
    for (int h = 0; h < 8; h++) {
        const float e = __expf(lg[h] - mx_sh[h]);
        a_sh[tid * 8 + h] = e;
        float v = e;
#pragma unroll
        for (int off = 16; off > 0; off >>= 1)
            v += __shfl_xor_sync(0xffffffffu, v, off);
        sm[h] = v;
    }
    __syncthreads();
    if (lane == 0)
#pragma unroll
        for (int h = 0; h < 8; h++) wred[warp * 8 + h] = sm[h];
    __syncthreads();
    if (tid < 8) {
        float v = 0.0f;
#pragma unroll
        for (int w = 0; w < 8; w++) v += wred[w * 8 + tid];
        g_sm[(r * NCH + ch) * 8 + tid] = v;
        g_mx[(r * NCH + ch) * 8 + tid] = mx_sh[tid];
    }

    const int h = warp;
    ull am = 0ull;
#pragma unroll 4
    for (int s = 0; s < CHUNK; s++) {
        const float a = a_sh[s * 8 + h];
        const ull mp = *(const ull*)&m_sh[s * L_MST + 2 * lane];
        ffma2(am, mp, pack2(a, a));
    }
    *(ull*)&g_am[((r * NCH + ch) * 8 + h) * 64 + 2 * lane] = am;
}

// ============================================================================
// Kernel C: combine chunks + o = am @ Wv^T -> g_o.
// ============================================================================
__global__ void __launch_bounds__(64, 8)
combine_kernel(const float* __restrict__ Wv) {
    __shared__ float wgt[8][8];
    __shared__ float den[8];
    __shared__ float am_sh[8 * 64];

    const int r   = blockIdx.x;
    const int tid = threadIdx.x;

    if (tid < 8) {
        const int h = tid;
        float mxg = -1e30f;
#pragma unroll
        for (int c = 0; c < NCH; c++) mxg = fmaxf(mxg, g_mx[(r * NCH + c) * 8 + h]);
        float d = 0.0f;
#pragma unroll
        for (int c = 0; c < NCH; c++) {
            const float w = __expf(g_mx[(r * NCH + c) * 8 + h] - mxg);
            wgt[h][c] = w;
            d = fmaf(g_sm[(r * NCH + c) * 8 + h], w, d);
        }
        den[h] = d;
    }
    __syncthreads();

    {
        const int h = tid >> 3, e0 = (tid & 7) * 8;
#pragma unroll
        for (int e = 0; e < 8; e++) {
            float s = 0.0f;
#pragma unroll
            for (int c = 0; c < NCH; c++)
                s = fmaf(g_am[((r * NCH + c) * 8 + h) * 64 + e0 + e], wgt[h][c], s);
            am_sh[h * 64 + e0 + e] = s;
        }
    }
    __syncthreads();

    {
        const int h = tid >> 3, cc = tid & 7;
        float acc = 0.0f;
        const float* wvr = Wv + cc * 64;
        const float* amr = am_sh + h * 64;
#pragma unroll
        for (int e = 0; e < 64; e++) acc = fmaf(amr[e], wvr[e], acc);
        g_o[r * HC + h * 8 + cc] = acc / den[tid >> 3];
    }
}

// ============================================================================
// Kernel B (persistent, pipelined HMMA): gate + out projection + residual.
// Grid 304, 128 threads. Each CTA loops over tiles (r, 128-row s-tile).
// m tiles prefetched f32 via cp.async double buffer; bf16 hi/lo split on the
// fly; t kept in registers between GEMMs (D-frag == A-frag layout).
// ============================================================================
#define G_GRID 304
#define G_NT   (RDIM * (SDIM / 128))     // 6144
#define BUFW   68                        // f32 row stride in m buffer
#define ASTW   36                        // weight row stride in words

#define G_BUF_FLOATS (128 * BUFW)        // per buffer
#define G_W_OFF  (2 * G_BUF_FLOATS)      // weights after 2 buffers (in floats)
#define G_SMEM_FLOATS (G_W_OFF + 4 * 64 * ASTW + 128)
#define G_SMEM_BYTES  (G_SMEM_FLOATS * 4)

__global__ void __launch_bounds__(128, 2)
gate_kernel(const float* __restrict__ m, const float* __restrict__ Wg,
            const float* __restrict__ bg, const float* __restrict__ Wo,
            const float* __restrict__ bo, const float* __restrict__ add_to,
            float* __restrict__ out) {
    extern __shared__ __align__(16) float sgf[];
    float* bufs[2] = { sgf, sgf + G_BUF_FLOATS };
    uint* wg_hi = (uint*)(sgf + G_W_OFF);
    uint* wg_lo = wg_hi + 64 * ASTW;
    uint* wo_hi = wg_lo + 64 * ASTW;
    uint* wo_lo = wo_hi + 64 * ASTW;
    float* bg_sh = (float*)(wo_lo + 64 * ASTW);
    float* bo_sh = bg_sh + 64;

    const int tid  = threadIdx.x;
    const int lane = tid & 31;
    const int warp = tid >> 5;
    const int g    = lane >> 2;
    const int tg   = lane & 3;
    const int rowbase = warp * 32;

    const uint buf_u32[2] = { smem_u32(bufs[0]), smem_u32(bufs[1]) };

    // ---- stage weights + biases ONCE ----
    for (int i = tid; i < 2048; i += 128) {
        const int row = i >> 5, kp = i & 31;
        {
            float2 w = *(const float2*)(Wg + row * 64 + kp * 2);
            uint hi, lo; split2(w.x, w.y, hi, lo);
            wg_hi[row * ASTW + kp] = hi;
            wg_lo[row * ASTW + kp] = lo;
        }
        {
            float2 w = *(const float2*)(Wo + row * 64 + kp * 2);
            uint hi, lo; split2(w.x, w.y, hi, lo);
            wo_hi[row * ASTW + kp] = hi;
            wo_lo[row * ASTW + kp] = lo;
        }
    }
    if (tid < 64) {
        bg_sh[tid] = bg[tid];
        bo_sh[tid] = bo[tid];
    }

    // ---- prologue: prefetch first tile ----
    int t0 = blockIdx.x;
    {
        const int r = t0 >> 4, sbase = (t0 & 15) * 128;
#pragma unroll
        for (int i = 0; i < 16; i++) {
            const int idx = tid + 128 * i;
            const int row = idx >> 4;
            const int c4  = (idx & 15) * 4;
            cp_async16(buf_u32[0] + (uint)(row * BUFW + c4) * 4,
                       m + ((size_t)r * SDIM + sbase + row) * CE + c4);
        }
        CP_COMMIT();
    }

    int cur = 0;
#pragma unroll 1
    for (int t = t0; t < G_NT; t += G_GRID, cur ^= 1) {
        const int r     = t >> 4;
        const int sbase = (t & 15) * 128;

        CP_WAIT0();
        __syncthreads();    // tile t visible to all; all warps done with buf cur^1

        // prefetch next tile into the other buffer (overlaps the GEMMs below)
        const int tn = t + G_GRID;
        if (tn < G_NT) {
            const int rn = tn >> 4, sbn = (tn & 15) * 128;
#pragma unroll
            for (int i = 0; i < 16; i++) {
                const int idx = tid + 128 * i;
                const int row = idx >> 4;
                const int c4  = (idx & 15) * 4;
                cp_async16(buf_u32[cur ^ 1] + (uint)(row * BUFW + c4) * 4,
                           m + ((size_t)rn * SDIM + sbn + row) * CE + c4);
            }
            CP_COMMIT();
        }

        const float* buf = bufs[cur];
        float d[2][8][4];

        // ===== GEMM1: gate logits = m @ Wg^T (A split on the fly) =====
#pragma unroll
        for (int mt = 0; mt < 2; mt++)
#pragma unroll
            for (int nt = 0; nt < 8; nt++)
#pragma unroll
                for (int q = 0; q < 4; q++) d[mt][nt][q] = 0.0f;

#pragma unroll
        for (int kt = 0; kt < 4; kt++) {
            uint ah[2][4], al[2][4];
#pragma unroll
            for (int mt = 0; mt < 2; mt++) {
                const int r0 = rowbase + mt * 16 + g;
                const float2 f0 = *(const float2*)&buf[r0 * BUFW + 16 * kt + 2 * tg];
                const float2 f1 = *(const float2*)&buf[(r0 + 8) * BUFW + 16 * kt + 2 * tg];
                const float2 f2 = *(const float2*)&buf[r0 * BUFW + 16 * kt + 2 * tg + 8];
                const float2 f3 = *(const float2*)&buf[(r0 + 8) * BUFW + 16 * kt + 2 * tg + 8];
                split2(f0.x, f0.y, ah[mt][0], al[mt][0]);
                split2(f1.x, f1.y, ah[mt][1], al[mt][1]);
                split2(f2.x, f2.y, ah[mt][2], al[mt][2]);
                split2(f3.x, f3.y, ah[mt][3], al[mt][3]);
            }
#pragma unroll
            for (int p = 0; p < 3; p++) {
                const uint* wb = (p == 1) ? wg_lo : wg_hi;
                const uint (*af)[4] = (p == 2) ? al : ah;
#pragma unroll
                for (int nt = 0; nt < 8; nt++) {
                    const uint b0 = wb[(nt * 8 + g) * ASTW + kt * 8 + tg];
                    const uint b1 = wb[(nt * 8 + g) * ASTW + kt * 8 + tg + 4];
                    mma_bf16(d[0][nt], af[0], b0, b1);
                    mma_bf16(d[1][nt], af[1], b0, b1);
                }
            }
        }

        // ===== epilogue 1 (registers only): t = sigmoid(d+bg)*o, split =====
        uint th[2][8][2], tl[2][8][2];
        {
            float ov0[8], ov1[8];
#pragma unroll
            for (int nt = 0; nt < 8; nt++) {
                const int c0 = nt * 8 + tg * 2;
                ov0[nt] = __ldg(&g_o[r * HC + c0]);
                ov1[nt] = __ldg(&g_o[r * HC + c0 + 1]);
            }
#pragma unroll
            for (int mt = 0; mt < 2; mt++) {
#pragma unroll
                for (int nt = 0; nt < 8; nt++) {
                    const int c0 = nt * 8 + tg * 2;
                    const float bg0 = bg_sh[c0], bg1 = bg_sh[c0 + 1];
                    const float t0 = fast_sigmoid(d[mt][nt][0] + bg0) * ov0[nt];
                    const float t1 = fast_sigmoid(d[mt][nt][1] + bg1) * ov1[nt];
                    const float t2 = fast_sigmoid(d[mt][nt][2] + bg0) * ov0[nt];
                    const float t3 = fast_sigmoid(d[mt][nt][3] + bg1) * ov1[nt];
                    split2(t0, t1, th[mt][nt][0], tl[mt][nt][0]);
                    split2(t2, t3, th[mt][nt][1], tl[mt][nt][1]);
                }
            }
        }

        // ===== GEMM2: out = t @ Wo^T (A straight from registers) =====
#pragma unroll
        for (int mt = 0; mt < 2; mt++)
#pragma unroll
            for (int nt = 0; nt < 8; nt++)
#pragma unroll
                for (int q = 0; q < 4; q++) d[mt][nt][q] = 0.0f;

#pragma unroll
        for (int p = 0; p < 3; p++) {
            const uint* wb = (p == 1) ? wo_lo : wo_hi;
#pragma unroll
            for (int kt = 0; kt < 4; kt++) {
                uint a[2][4];
#pragma unroll
                for (int mt = 0; mt < 2; mt++) {
                    if (p == 2) {
                        a[mt][0] = tl[mt][2 * kt][0];
                        a[mt][1] = tl[mt][2 * kt][1];
                        a[mt][2] = tl[mt][2 * kt + 1][0];
                        a[mt][3] = tl[mt][2 * kt + 1][1];
                    } else {
                        a[mt][0] = th[mt][2 * kt][0];
                        a[mt][1] = th[mt][2 * kt][1];
                        a[mt][2] = th[mt][2 * kt + 1][0];
                        a[mt][3] = th[mt][2 * kt + 1][1];
                    }
                }
#pragma unroll
                for (int nt = 0; nt < 8; nt++) {
                    const uint b0 = wb[(nt * 8 + g) * ASTW + kt * 8 + tg];
                    const uint b1 = wb[(nt * 8 + g) * ASTW + kt * 8 + tg + 4];
                    mma_bf16(d[0][nt], a[0], b0, b1);
                    mma_bf16(d[1][nt], a[1], b0, b1);
                }
            }
        }

        // ===== epilogue 2: out[s][r][:] = D + bo + add_to =====
#pragma unroll
        for (int mt = 0; mt < 2; mt++) {
#pragma unroll
            for (int nt = 0; nt < 8; nt++) {
                const int c0 = nt * 8 + tg * 2;
                const float bo0 = bo_sh[c0], bo1 = bo_sh[c0 + 1];
                const int r0 = rowbase + mt * 16 + g;
                {
                    const size_t base = ((size_t)(sbase + r0) * RDIM + r) * CE + c0;
                    const float2 av = *(const float2*)(add_to + base);
                    float2 ov;
                    ov.x = d[mt][nt][0] + bo0 + av.x;
                    ov.y = d[mt][nt][1] + bo1 + av.y;
                    *(float2*)(out + base) = ov;
                }
                {
                    const size_t base = ((size_t)(sbase + r0 + 8) * RDIM + r) * CE + c0;
                    const float2 av = *(const float2*)(add_to + base);
                    float2 ov;
                    ov.x = d[mt][nt][2] + bo0 + av.x;
                    ov.y = d[mt][nt][3] + bo1 + av.y;
                    *(float2*)(out + base) = ov;
                }
            }
        }
    }
}

// ============================================================================
extern "C" void kernel_launch(void* const* d_in, const int* in_sizes, int n_in,
                              void* d_out, int out_size) {
    const float* m      = (const float*)d_in[0];
    const float* mask   = (const float*)d_in[1];
    const float* Wq     = (const float*)d_in[2];
    const float* Wk     = (const float*)d_in[3];
    const float* Wv     = (const float*)d_in[4];
    const float* Wg     = (const float*)d_in[5];
    const float* bg     = (const float*)d_in[6];
    const float* Wo     = (const float*)d_in[7];
    const float* bo     = (const float*)d_in[8];
    const float* add_to = (const float*)d_in[9];
    float* out = (float*)d_out;

    cudaFuncSetAttribute(logits_kernel, cudaFuncAttributeMaxDynamicSharedMemorySize, L_BYTES);
    cudaFuncSetAttribute(gate_kernel, cudaFuncAttributeMaxDynamicSharedMemorySize, G_SMEM_BYTES);

    qpool_kernel<<<RDIM, 256>>>(m, mask, Wq, Wk);
    logits_kernel<<<dim3(NCH, RDIM), 256, L_BYTES>>>(m, mask);
    combine_kernel<<<RDIM, 64>>>(Wv);
    gate_kernel<<<G_GRID, 128, G_SMEM_BYTES>>>(m, Wg, bg, Wo, bo, add_to, out);
}

// round 8
// speedup vs baseline: 2.4795x; 1.2320x over previous
#include <cuda_runtime.h>
#include <cuda_bf16.h>
#include <cstdint>

typedef unsigned long long ull;
typedef unsigned int uint;

// ================= helpers =================
__device__ __forceinline__ void ffma2(ull& d, ull a, ull b) {
    asm("fma.rn.f32x2 %0, %1, %2, %0;" : "+l"(d) : "l"(a), "l"(b));
}
__device__ __forceinline__ ull pack2(float x, float y) {
    ull d; asm("mov.b64 %0, {%1, %2};" : "=l"(d) : "f"(x), "f"(y)); return d;
}
__device__ __forceinline__ float fast_sigmoid(float x) {
    float t;
    asm("tanh.approx.f32 %0, %1;" : "=f"(t) : "f"(x * 0.5f));
    return fmaf(t, 0.5f, 0.5f);
}
__device__ __forceinline__ uint bfpack(float x, float y) {
    __nv_bfloat16 bx = __float2bfloat16(x), by = __float2bfloat16(y);
    return (uint)__bfloat16_as_ushort(bx) | ((uint)__bfloat16_as_ushort(by) << 16);
}
__device__ __forceinline__ void split2(float x, float y, uint& hi, uint& lo) {
    __nv_bfloat16 hx = __float2bfloat16(x), hy = __float2bfloat16(y);
    hi = (uint)__bfloat16_as_ushort(hx) | ((uint)__bfloat16_as_ushort(hy) << 16);
    lo = bfpack(x - __bfloat162float(hx), y - __bfloat162float(hy));
}
__device__ __forceinline__ void mma_bf16(float* d, const uint* a, uint b0, uint b1) {
    asm volatile(
        "mma.sync.aligned.m16n8k16.row.col.f32.bf16.bf16.f32 "
        "{%0,%1,%2,%3}, {%4,%5,%6,%7}, {%8,%9}, {%0,%1,%2,%3};"
        : "+f"(d[0]), "+f"(d[1]), "+f"(d[2]), "+f"(d[3])
        : "r"(a[0]), "r"(a[1]), "r"(a[2]), "r"(a[3]), "r"(b0), "r"(b1));
}
__device__ __forceinline__ uint smem_u32(const void* p) {
    uint a;
    asm("{ .reg .u64 t; cvta.to.shared.u64 t, %1; cvt.u32.u64 %0, t; }" : "=r"(a) : "l"(p));
    return a;
}
__device__ __forceinline__ void cp_async16(uint saddr, const void* gptr) {
    asm volatile("cp.async.cg.shared.global [%0], [%1], 16;" :: "r"(saddr), "l"(gptr));
}
#define CP_COMMIT() asm volatile("cp.async.commit_group;" ::: "memory")
#define CP_WAIT0()  asm volatile("cp.async.wait_group 0;" ::: "memory")

// ================= constants =================
#define RDIM 384
#define SDIM 2048
#define CE   64
#define HC   64
#define QSCALE 0.35355339059327373f
#define NCH  8
#define CHUNK 256

// ================= scratch =================
__device__ float g_o[RDIM * HC];
__device__ float g_kv[(size_t)RDIM * SDIM * 16];    // [r][s][c: 0..7=k, 8..15=v]
__device__ float g_poolq[RDIM * 64 * 64];           // [r][tile*4+warp][e]
__device__ float g_poold[RDIM * 64];                // [r][tile*4+warp]
__device__ float g_qproj[RDIM * 64];                // [r][h*8+c]
__device__ float g_ov[RDIM * NCH * 64];             // [r][ch][h*8+c]
__device__ float g_mx[RDIM * NCH * 8];
__device__ float g_sm[RDIM * NCH * 8];

// ============================================================================
// K1: persistent pipelined kv projection + pooling partials.
// Grid 304, 128 threads; tiles (r, 128-row s). GEMM m@Wkv^T (N=16) via HMMA.
// ============================================================================
#define KV_GRID 304
#define KV_NT   (RDIM * (SDIM / 128))
#define BUFW    68
#define ASTW    36
#define KV_BUF_FLOATS (128 * BUFW)
#define KV_W_OFF (2 * KV_BUF_FLOATS)
#define KV_SMEM_FLOATS (KV_W_OFF + 2 * 16 * ASTW)
#define KV_SMEM_BYTES  (KV_SMEM_FLOATS * 4)

__global__ void __launch_bounds__(128, 2)
kv_kernel(const float* __restrict__ m, const float* __restrict__ mask,
          const float* __restrict__ Wk, const float* __restrict__ Wv) {
    extern __shared__ __align__(16) float skf[];
    float* bufs[2] = { skf, skf + KV_BUF_FLOATS };
    uint* wkv_hi = (uint*)(skf + KV_W_OFF);
    uint* wkv_lo = wkv_hi + 16 * ASTW;

    const int tid  = threadIdx.x;
    const int lane = tid & 31;
    const int warp = tid >> 5;
    const int g    = lane >> 2;
    const int tg   = lane & 3;
    const int rowbase = warp * 32;

    const uint buf_u32[2] = { smem_u32(bufs[0]), smem_u32(bufs[1]) };

    // stage Wkv (rows 0..7 = Wk, 8..15 = Wv) hi/lo once
    for (int i = tid; i < 512; i += 128) {
        const int row = i >> 5, kp = i & 31;
        const float* W = (row < 8) ? (Wk + row * 64) : (Wv + (row - 8) * 64);
        float2 w = *(const float2*)(W + kp * 2);
        uint hi, lo; split2(w.x, w.y, hi, lo);
        wkv_hi[row * ASTW + kp] = hi;
        wkv_lo[row * ASTW + kp] = lo;
    }

    int t0 = blockIdx.x;
    {
        const int r = t0 >> 4, sbase = (t0 & 15) * 128;
#pragma unroll
        for (int i = 0; i < 16; i++) {
            const int idx = tid + 128 * i;
            const int row = idx >> 4;
            const int c4  = (idx & 15) * 4;
            cp_async16(buf_u32[0] + (uint)(row * BUFW + c4) * 4,
                       m + ((size_t)r * SDIM + sbase + row) * CE + c4);
        }
        CP_COMMIT();
    }

    int cur = 0;
#pragma unroll 1
    for (int t = t0; t < KV_NT; t += KV_GRID, cur ^= 1) {
        const int r     = t >> 4;
        const int ts    = t & 15;
        const int sbase = ts * 128;

        CP_WAIT0();
        __syncthreads();

        const int tn = t + KV_GRID;
        if (tn < KV_NT) {
            const int rn = tn >> 4, sbn = (tn & 15) * 128;
#pragma unroll
            for (int i = 0; i < 16; i++) {
                const int idx = tid + 128 * i;
                const int row = idx >> 4;
                const int c4  = (idx & 15) * 4;
                cp_async16(buf_u32[cur ^ 1] + (uint)(row * BUFW + c4) * 4,
                           m + ((size_t)rn * SDIM + sbn + row) * CE + c4);
            }
            CP_COMMIT();
        }

        const float* buf = bufs[cur];

        // ---- pooling partials: warp covers rows [32w,32w+32), lane = e-pair ----
        {
            const float mskv = mask[(size_t)r * SDIM + sbase + rowbase + lane];
            ull qn = 0ull;
            float qden = 0.0f;
#pragma unroll 8
            for (int i = 0; i < 32; i++) {
                const float msk = __shfl_sync(0xffffffffu, mskv, i);
                const ull mv = *(const ull*)&buf[(rowbase + i) * BUFW + 2 * lane];
                ffma2(qn, mv, pack2(msk, msk));
                qden += msk;
            }
            const int p = (r * 16 + ts) * 4 + warp;
            *(ull*)&g_poolq[(size_t)p * 64 + 2 * lane] = qn;
            if (lane == 0) g_poold[p] = qden;
        }

        // ---- kv GEMM: D[mt][nt][4], N=16 ----
        float d[2][2][4];
#pragma unroll
        for (int mt = 0; mt < 2; mt++)
#pragma unroll
            for (int nt = 0; nt < 2; nt++)
#pragma unroll
                for (int q = 0; q < 4; q++) d[mt][nt][q] = 0.0f;

#pragma unroll
        for (int kt = 0; kt < 4; kt++) {
            uint ah[2][4], al[2][4];
#pragma unroll
            for (int mt = 0; mt < 2; mt++) {
                const int r0 = rowbase + mt * 16 + g;
                const float2 f0 = *(const float2*)&buf[r0 * BUFW + 16 * kt + 2 * tg];
                const float2 f1 = *(const float2*)&buf[(r0 + 8) * BUFW + 16 * kt + 2 * tg];
                const float2 f2 = *(const float2*)&buf[r0 * BUFW + 16 * kt + 2 * tg + 8];
                const float2 f3 = *(const float2*)&buf[(r0 + 8) * BUFW + 16 * kt + 2 * tg + 8];
                split2(f0.x, f0.y, ah[mt][0], al[mt][0]);
                split2(f1.x, f1.y, ah[mt][1], al[mt][1]);
                split2(f2.x, f2.y, ah[mt][2], al[mt][2]);
                split2(f3.x, f3.y, ah[mt][3], al[mt][3]);
            }
#pragma unroll
            for (int p = 0; p < 3; p++) {
                const uint* wb = (p == 1) ? wkv_lo : wkv_hi;
                const uint (*af)[4] = (p == 2) ? al : ah;
#pragma unroll
                for (int nt = 0; nt < 2; nt++) {
                    const uint b0 = wb[(nt * 8 + g) * ASTW + kt * 8 + tg];
                    const uint b1 = wb[(nt * 8 + g) * ASTW + kt * 8 + tg + 4];
                    mma_bf16(d[0][nt], af[0], b0, b1);
                    mma_bf16(d[1][nt], af[1], b0, b1);
                }
            }
        }

        // ---- store kv [r][s][16] ----
#pragma unroll
        for (int mt = 0; mt < 2; mt++) {
#pragma unroll
            for (int nt = 0; nt < 2; nt++) {
                const int c0 = nt * 8 + 2 * tg;
                const int r0 = rowbase + mt * 16 + g;
                *(float2*)&g_kv[((size_t)r * SDIM + sbase + r0) * 16 + c0] =
                    make_float2(d[mt][nt][0], d[mt][nt][1]);
                *(float2*)&g_kv[((size_t)r * SDIM + sbase + r0 + 8) * 16 + c0] =
                    make_float2(d[mt][nt][2], d[mt][nt][3]);
            }
        }
    }
}

// ============================================================================
// K2: reduce pooling partials -> q -> qproj.  384 CTAs x 64 threads.
// ============================================================================
__global__ void __launch_bounds__(64, 8)
qk2_kernel(const float* __restrict__ Wq) {
    __shared__ float qpool[64];
    const int r   = blockIdx.x;
    const int tid = threadIdx.x;

    float qs = 0.0f, qd = 0.0f;
#pragma unroll 8
    for (int p = 0; p < 64; p++) {
        qs += g_poolq[(size_t)(r * 64 + p) * 64 + tid];
        qd += g_poold[r * 64 + p];
    }
    qpool[tid] = qs / (qd + 1e-10f);
    __syncthreads();

    float acc = 0.0f;
    const float* wqr = Wq + tid * 64;
#pragma unroll
    for (int e = 0; e < 64; e++) acc = fmaf(qpool[e], wqr[e], acc);
    g_qproj[r * 64 + tid] = acc * QSCALE;
}

// ============================================================================
// K3: per (ch, r): logits from k, chunk softmax partials, partial o = a^T v.
// 256 threads; thread owns one s-row of the chunk.
// ============================================================================
__global__ void __launch_bounds__(256, 3)
attn3_kernel(const float* __restrict__ mask) {
    __shared__ float v_sh[256 * 9];
    __shared__ float a_sh[256 * 8];
    __shared__ float qp_sh[64];
    __shared__ float wred[64];
    __shared__ float mx_sh[8];

    const int tid  = threadIdx.x;
    const int lane = tid & 31;
    const int warp = tid >> 5;
    const int ch   = blockIdx.x;
    const int r    = blockIdx.y;
    const int sbase = ch * CHUNK;

    if (tid < 64) qp_sh[tid] = g_qproj[r * 64 + tid];

    // load own kv row
    const float* kvrow = &g_kv[((size_t)r * SDIM + sbase + tid) * 16];
    const float4 k01 = *(const float4*)(kvrow);
    const float4 k23 = *(const float4*)(kvrow + 4);
    const float4 v01 = *(const float4*)(kvrow + 8);
    const float4 v23 = *(const float4*)(kvrow + 12);
    float kreg[8] = { k01.x, k01.y, k01.z, k01.w, k23.x, k23.y, k23.z, k23.w };
    v_sh[tid * 9 + 0] = v01.x; v_sh[tid * 9 + 1] = v01.y;
    v_sh[tid * 9 + 2] = v01.z; v_sh[tid * 9 + 3] = v01.w;
    v_sh[tid * 9 + 4] = v23.x; v_sh[tid * 9 + 5] = v23.y;
    v_sh[tid * 9 + 6] = v23.z; v_sh[tid * 9 + 7] = v23.w;

    const float mymsk = mask[(size_t)r * SDIM + sbase + tid];
    __syncthreads();

    float lg[8];
    const float bias = (mymsk - 1.0f) * 1e9f;
#pragma unroll
    for (int h = 0; h < 8; h++) {
        float v = bias;
#pragma unroll
        for (int c = 0; c < 8; c++) v = fmaf(qp_sh[h * 8 + c], kreg[c], v);
        lg[h] = v;
    }

    // chunk max per h
    float wm[8];
#pragma unroll
    for (int h = 0; h < 8; h++) {
        float v = lg[h];
#pragma unroll
        for (int off = 16; off > 0; off >>= 1)
            v = fmaxf(v, __shfl_xor_sync(0xffffffffu, v, off));
        wm[h] = v;
    }
    if (lane == 0)
#pragma unroll
        for (int h = 0; h < 8; h++) wred[warp * 8 + h] = wm[h];
    __syncthreads();
    if (tid < 8) {
        float v = -1e30f;
#pragma unroll
        for (int w = 0; w < 8; w++) v = fmaxf(v, wred[w * 8 + tid]);
        mx_sh[tid] = v;
    }
    __syncthreads();

    float sm[8];
#pragma unroll
    for (int h = 0; h < 8; h++) {
        const float e = __expf(lg[h] - mx_sh[h]);
        a_sh[tid * 8 + h] = e;
        float v = e;
#pragma unroll
        for (int off = 16; off > 0; off >>= 1)
            v += __shfl_xor_sync(0xffffffffu, v, off);
        sm[h] = v;
    }
    __syncthreads();
    if (lane == 0)
#pragma unroll
        for (int h = 0; h < 8; h++) wred[warp * 8 + h] = sm[h];
    __syncthreads();
    if (tid < 8) {
        float v = 0.0f;
#pragma unroll
        for (int w = 0; w < 8; w++) v += wred[w * 8 + tid];
        g_sm[(r * NCH + ch) * 8 + tid] = v;
        g_mx[(r * NCH + ch) * 8 + tid] = mx_sh[tid];
    }

    // partial o[h][c]: warp = h; lane: c = lane&7, sgrp = lane>>3 (rows 4i+sgrp)
    {
        const int h = warp;
        const int c = lane & 7;
        const int sgrp = lane >> 3;
        float acc = 0.0f;
#pragma unroll 8
        for (int i = 0; i < 64; i++) {
            const int row = 4 * i + sgrp;
            acc = fmaf(a_sh[row * 8 + h], v_sh[row * 9 + c], acc);
        }
        acc += __shfl_xor_sync(0xffffffffu, acc, 8);
        acc += __shfl_xor_sync(0xffffffffu, acc, 16);
        if (lane < 8)
            g_ov[(r * NCH + ch) * 64 + h * 8 + c] = acc;
    }
}

// ============================================================================
// C': combine chunks -> g_o.  384 CTAs x 64 threads.
// ============================================================================
__global__ void __launch_bounds__(64, 8)
combine2_kernel() {
    __shared__ float wgt[8][8];
    __shared__ float den[8];

    const int r   = blockIdx.x;
    const int tid = threadIdx.x;

    if (tid < 8) {
        const int h = tid;
        float mxg = -1e30f;
#pragma unroll
        for (int c = 0; c < NCH; c++) mxg = fmaxf(mxg, g_mx[(r * NCH + c) * 8 + h]);
        float d = 0.0f;
#pragma unroll
        for (int c = 0; c < NCH; c++) {
            const float w = __expf(g_mx[(r * NCH + c) * 8 + h] - mxg);
            wgt[h][c] = w;
            d = fmaf(g_sm[(r * NCH + c) * 8 + h], w, d);
        }
        den[h] = d;
    }
    __syncthreads();

    const int h = tid >> 3;
    float acc = 0.0f;
#pragma unroll
    for (int c = 0; c < NCH; c++)
        acc = fmaf(g_ov[(r * NCH + c) * 64 + tid], wgt[h][c], acc);
    g_o[r * HC + tid] = acc / den[h];
}

// ============================================================================
// Kernel B (persistent, pipelined HMMA): gate + out projection + residual.
// (unchanged from round 7)
// ============================================================================
#define G_GRID 304
#define G_NT   (RDIM * (SDIM / 128))
#define G_BUF_FLOATS (128 * BUFW)
#define G_W_OFF  (2 * G_BUF_FLOATS)
#define G_SMEM_FLOATS (G_W_OFF + 4 * 64 * ASTW + 128)
#define G_SMEM_BYTES  (G_SMEM_FLOATS * 4)

__global__ void __launch_bounds__(128, 2)
gate_kernel(const float* __restrict__ m, const float* __restrict__ Wg,
            const float* __restrict__ bg, const float* __restrict__ Wo,
            const float* __restrict__ bo, const float* __restrict__ add_to,
            float* __restrict__ out) {
    extern __shared__ __align__(16) float sgf[];
    float* bufs[2] = { sgf, sgf + G_BUF_FLOATS };
    uint* wg_hi = (uint*)(sgf + G_W_OFF);
    uint* wg_lo = wg_hi + 64 * ASTW;
    uint* wo_hi = wg_lo + 64 * ASTW;
    uint* wo_lo = wo_hi + 64 * ASTW;
    float* bg_sh = (float*)(wo_lo + 64 * ASTW);
    float* bo_sh = bg_sh + 64;

    const int tid  = threadIdx.x;
    const int lane = tid & 31;
    const int warp = tid >> 5;
    const int g    = lane >> 2;
    const int tg   = lane & 3;
    const int rowbase = warp * 32;

    const uint buf_u32[2] = { smem_u32(bufs[0]), smem_u32(bufs[1]) };

    for (int i = tid; i < 2048; i += 128) {
        const int row = i >> 5, kp = i & 31;
        {
            float2 w = *(const float2*)(Wg + row * 64 + kp * 2);
            uint hi, lo; split2(w.x, w.y, hi, lo);
            wg_hi[row * ASTW + kp] = hi;
            wg_lo[row * ASTW + kp] = lo;
        }
        {
            float2 w = *(const float2*)(Wo + row * 64 + kp * 2);
            uint hi, lo; split2(w.x, w.y, hi, lo);
            wo_hi[row * ASTW + kp] = hi;
            wo_lo[row * ASTW + kp] = lo;
        }
    }
    if (tid < 64) {
        bg_sh[tid] = bg[tid];
        bo_sh[tid] = bo[tid];
    }

    int t0 = blockIdx.x;
    {
        const int r = t0 >> 4, sbase = (t0 & 15) * 128;
#pragma unroll
        for (int i = 0; i < 16; i++) {
            const int idx = tid + 128 * i;
            const int row = idx >> 4;
            const int c4  = (idx & 15) * 4;
            cp_async16(buf_u32[0] + (uint)(row * BUFW + c4) * 4,
                       m + ((size_t)r * SDIM + sbase + row) * CE + c4);
        }
        CP_COMMIT();
    }

    int cur = 0;
#pragma unroll 1
    for (int t = t0; t < G_NT; t += G_GRID, cur ^= 1) {
        const int r     = t >> 4;
        const int sbase = (t & 15) * 128;

        CP_WAIT0();
        __syncthreads();

        const int tn = t + G_GRID;
        if (tn < G_NT) {
            const int rn = tn >> 4, sbn = (tn & 15) * 128;
#pragma unroll
            for (int i = 0; i < 16; i++) {
                const int idx = tid + 128 * i;
                const int row = idx >> 4;
                const int c4  = (idx & 15) * 4;
                cp_async16(buf_u32[cur ^ 1] + (uint)(row * BUFW + c4) * 4,
                           m + ((size_t)rn * SDIM + sbn + row) * CE + c4);
            }
            CP_COMMIT();
        }

        const float* buf = bufs[cur];
        float d[2][8][4];

#pragma unroll
        for (int mt = 0; mt < 2; mt++)
#pragma unroll
            for (int nt = 0; nt < 8; nt++)
#pragma unroll
                for (int q = 0; q < 4; q++) d[mt][nt][q] = 0.0f;

#pragma unroll
        for (int kt = 0; kt < 4; kt++) {
            uint ah[2][4], al[2][4];
#pragma unroll
            for (int mt = 0; mt < 2; mt++) {
                const int r0 = rowbase + mt * 16 + g;
                const float2 f0 = *(const float2*)&buf[r0 * BUFW + 16 * kt + 2 * tg];
                const float2 f1 = *(const float2*)&buf[(r0 + 8) * BUFW + 16 * kt + 2 * tg];
                const float2 f2 = *(const float2*)&buf[r0 * BUFW + 16 * kt + 2 * tg + 8];
                const float2 f3 = *(const float2*)&buf[(r0 + 8) * BUFW + 16 * kt + 2 * tg + 8];
                split2(f0.x, f0.y, ah[mt][0], al[mt][0]);
                split2(f1.x, f1.y, ah[mt][1], al[mt][1]);
                split2(f2.x, f2.y, ah[mt][2], al[mt][2]);
                split2(f3.x, f3.y, ah[mt][3], al[mt][3]);
            }
#pragma unroll
            for (int p = 0; p < 3; p++) {
                const uint* wb = (p == 1) ? wg_lo : wg_hi;
                const uint (*af)[4] = (p == 2) ? al : ah;
#pragma unroll
                for (int nt = 0; nt < 8; nt++) {
                    const uint b0 = wb[(nt * 8 + g) * ASTW + kt * 8 + tg];
                    const uint b1 = wb[(nt * 8 + g) * ASTW + kt * 8 + tg + 4];
                    mma_bf16(d[0][nt], af[0], b0, b1);
                    mma_bf16(d[1][nt], af[1], b0, b1);
                }
            }
        }

        uint th[2][8][2], tl[2][8][2];
        {
            float ov0[8], ov1[8];
#pragma unroll
            for (int nt = 0; nt < 8; nt++) {
                const int c0 = nt * 8 + tg * 2;
                ov0[nt] = __ldg(&g_o[r * HC + c0]);
                ov1[nt] = __ldg(&g_o[r * HC + c0 + 1]);
            }
#pragma unroll
            for (int mt = 0; mt < 2; mt++) {
#pragma unroll
                for (int nt = 0; nt < 8; nt++) {
                    const int c0 = nt * 8 + tg * 2;
                    const float bg0 = bg_sh[c0], bg1 = bg_sh[c0 + 1];
                    const float t0 = fast_sigmoid(d[mt][nt][0] + bg0) * ov0[nt];
                    const float t1 = fast_sigmoid(d[mt][nt][1] + bg1) * ov1[nt];
                    const float t2 = fast_sigmoid(d[mt][nt][2] + bg0) * ov0[nt];
                    const float t3 = fast_sigmoid(d[mt][nt][3] + bg1) * ov1[nt];
                    split2(t0, t1, th[mt][nt][0], tl[mt][nt][0]);
                    split2(t2, t3, th[mt][nt][1], tl[mt][nt][1]);
                }
            }
        }

#pragma unroll
        for (int mt = 0; mt < 2; mt++)
#pragma unroll
            for (int nt = 0; nt < 8; nt++)
#pragma unroll
                for (int q = 0; q < 4; q++) d[mt][nt][q] = 0.0f;

#pragma unroll
        for (int p = 0; p < 3; p++) {
            const uint* wb = (p == 1) ? wo_lo : wo_hi;
#pragma unroll
            for (int kt = 0; kt < 4; kt++) {
                uint a[2][4];
#pragma unroll
                for (int mt = 0; mt < 2; mt++) {
                    if (p == 2) {
                        a[mt][0] = tl[mt][2 * kt][0];
                        a[mt][1] = tl[mt][2 * kt][1];
                        a[mt][2] = tl[mt][2 * kt + 1][0];
                        a[mt][3] = tl[mt][2 * kt + 1][1];
                    } else {
                        a[mt][0] = th[mt][2 * kt][0];
                        a[mt][1] = th[mt][2 * kt][1];
                        a[mt][2] = th[mt][2 * kt + 1][0];
                        a[mt][3] = th[mt][2 * kt + 1][1];
                    }
                }
#pragma unroll
                for (int nt = 0; nt < 8; nt++) {
                    const uint b0 = wb[(nt * 8 + g) * ASTW + kt * 8 + tg];
                    const uint b1 = wb[(nt * 8 + g) * ASTW + kt * 8 + tg + 4];
                    mma_bf16(d[0][nt], a[0], b0, b1);
                    mma_bf16(d[1][nt], a[1], b0, b1);
                }
            }
        }

#pragma unroll
        for (int mt = 0; mt < 2; mt++) {
#pragma unroll
            for (int nt = 0; nt < 8; nt++) {
                const int c0 = nt * 8 + tg * 2;
                const float bo0 = bo_sh[c0], bo1 = bo_sh[c0 + 1];
                const int r0 = rowbase + mt * 16 + g;
                {
                    const size_t base = ((size_t)(sbase + r0) * RDIM + r) * CE + c0;
                    const float2 av = *(const float2*)(add_to + base);
                    float2 ov;
                    ov.x = d[mt][nt][0] + bo0 + av.x;
                    ov.y = d[mt][nt][1] + bo1 + av.y;
                    *(float2*)(out + base) = ov;
                }
                {
                    const size_t base = ((size_t)(sbase + r0 + 8) * RDIM + r) * CE + c0;
                    const float2 av = *(const float2*)(add_to + base);
                    float2 ov;
                    ov.x = d[mt][nt][2] + bo0 + av.x;
                    ov.y = d[mt][nt][3] + bo1 + av.y;
                    *(float2*)(out + base) = ov;
                }
            }
        }
    }
}

// ============================================================================
extern "C" void kernel_launch(void* const* d_in, const int* in_sizes, int n_in,
                              void* d_out, int out_size) {
    const float* m      = (const float*)d_in[0];
    const float* mask   = (const float*)d_in[1];
    const float* Wq     = (const float*)d_in[2];
    const float* Wk     = (const float*)d_in[3];
    const float* Wv     = (const float*)d_in[4];
    const float* Wg     = (const float*)d_in[5];
    const float* bg     = (const float*)d_in[6];
    const float* Wo     = (const float*)d_in[7];
    const float* bo     = (const float*)d_in[8];
    const float* add_to = (const float*)d_in[9];
    float* out = (float*)d_out;

    cudaFuncSetAttribute(kv_kernel, cudaFuncAttributeMaxDynamicSharedMemorySize, KV_SMEM_BYTES);
    cudaFuncSetAttribute(gate_kernel, cudaFuncAttributeMaxDynamicSharedMemorySize, G_SMEM_BYTES);

    kv_kernel<<<KV_GRID, 128, KV_SMEM_BYTES>>>(m, mask, Wk, Wv);
    qk2_kernel<<<RDIM, 64>>>(Wq);
    attn3_kernel<<<dim3(NCH, RDIM), 256>>>(mask);
    combine2_kernel<<<RDIM, 64>>>();
    gate_kernel<<<G_GRID, 128, G_SMEM_BYTES>>>(m, Wg, bg, Wo, bo, add_to, out);
}